// round 5
// baseline (speedup 1.0000x reference)
#include <cuda_runtime.h>
#include <cuda_bf16.h>
#include <math.h>
#include <stdint.h>

#define N_ROWS 8192
#define FD 128
#define INV_T 14.2857142857142857f   // 1/0.07
#define NBATCH 512
#define NCLASS 16

// ---------------- device-global scratch ----------------
__device__ uint4  g_fhi_sw[N_ROWS * 16];
__device__ uint4  g_flo_sw[N_ROWS * 16];
__device__ float  g_F[NCLASS * FD];
__device__ int    g_cnt[NCLASS];
__device__ float  g_Bb[NBATCH * FD];
__device__ __align__(16) float2 g_slot[N_ROWS * 256];  // per-(row, rb*4+wy) LSE partials
__device__ float  g_noise_arr[NBATCH];
__device__ float  g_class_arr[1024];

// ---------------- helpers ----------------
__device__ __forceinline__ uint32_t smem_u32(const void* p) {
    uint32_t a;
    asm("{ .reg .u64 t; cvta.to.shared.u64 t, %1; cvt.u32.u64 %0, t; }" : "=r"(a) : "l"(p));
    return a;
}
__device__ __forceinline__ void cp16(uint32_t s, const void* g) {
    asm volatile("cp.async.cg.shared.global [%0], [%1], 16;" :: "r"(s), "l"(g) : "memory");
}
#define CP_COMMIT() asm volatile("cp.async.commit_group;" ::: "memory")
#define CP_WAIT1()  asm volatile("cp.async.wait_group 1;" ::: "memory")
#define CP_WAIT0()  asm volatile("cp.async.wait_group 0;" ::: "memory")

#define LDSM4(R, addr) \
    asm volatile("ldmatrix.sync.aligned.m8n8.x4.shared.b16 {%0,%1,%2,%3}, [%4];" \
        : "=r"((R)[0]), "=r"((R)[1]), "=r"((R)[2]), "=r"((R)[3]) : "r"(addr))

#define MMA(C, A, B0, B1) \
    asm volatile("mma.sync.aligned.m16n8k16.row.col.f32.bf16.bf16.f32 " \
        "{%0,%1,%2,%3}, {%4,%5,%6,%7}, {%8,%9}, {%0,%1,%2,%3};" \
        : "+f"((C)[0]), "+f"((C)[1]), "+f"((C)[2]), "+f"((C)[3]) \
        : "r"((A)[0]), "r"((A)[1]), "r"((A)[2]), "r"((A)[3]), "r"(B0), "r"(B1))

__device__ __forceinline__ uint32_t pack_bf2(__nv_bfloat16 a, __nv_bfloat16 b) {
    __nv_bfloat162 t(a, b);
    return *reinterpret_cast<uint32_t*>(&t);
}

// ---------------- kernel 1: fused setup ----------------
// blocks [0,1024): init slot table; [1024,1536): hi/lo prep; [1536,1792): batch sums + noise
__global__ void setup_kernel(const float* __restrict__ f, const int* __restrict__ labels) {
    __shared__ float red[8];
    int blk = blockIdx.x;
    int t = threadIdx.x;
    if (blk < 1024) {
        float4* p = (float4*)g_slot;
        int base = (blk * 256 + t) * 4;
        float4 z = make_float4(-1.0e30f, 0.f, -1.0e30f, 0.f);
#pragma unroll
        for (int k = 0; k < 4; k++) p[base + k] = z;
    } else if (blk < 1536) {
        int idx = (blk - 1024) * 256 + t;   // 0..131071, one 16B chunk
        int row = idx >> 4;
        int c = idx & 15;
        float4 v0 = ((const float4*)f)[row * 32 + c * 2];
        float4 v1 = ((const float4*)f)[row * 32 + c * 2 + 1];
        float vs[8] = { v0.x, v0.y, v0.z, v0.w, v1.x, v1.y, v1.z, v1.w };
        uint32_t hi[4], lo[4];
#pragma unroll
        for (int k = 0; k < 4; k++) {
            float a = vs[2 * k], b = vs[2 * k + 1];
            __nv_bfloat16 ha = __float2bfloat16(a), hb = __float2bfloat16(b);
            __nv_bfloat16 la = __float2bfloat16(a - __bfloat162float(ha));
            __nv_bfloat16 lb = __float2bfloat16(b - __bfloat162float(hb));
            hi[k] = pack_bf2(ha, hb);
            lo[k] = pack_bf2(la, lb);
        }
        int dst = ((row >> 7) << 11) + ((row & 127) << 4) + (c ^ (row & 7));
        g_fhi_sw[dst] = make_uint4(hi[0], hi[1], hi[2], hi[3]);
        g_flo_sw[dst] = make_uint4(lo[0], lo[1], lo[2], lo[3]);
    } else {
        int b = (blk - 1536) * 2 + (t >> 7);
        int tt = t & 127;
        float s16 = 0.f, s8a = 0.f, s8b = 0.f, ssq = 0.f;
#pragma unroll
        for (int r = 0; r < 16; r++) {
            float v = f[(b * 16 + r) * FD + tt];
            s16 += v;
            if (r < 8) s8a += v; else s8b += v;
            ssq += v * v;
        }
        g_Bb[b * FD + tt] = s16;
        float c = s8a * s8a + s8b * s8b - ssq;
#pragma unroll
        for (int sh = 16; sh > 0; sh >>= 1)
            c += __shfl_xor_sync(0xffffffffu, c, sh);
        if ((t & 31) == 0) red[t >> 5] = c;
        __syncthreads();
        if ((t & 127) == 0) {
            int w0 = t >> 5;   // 0 or 4
            g_noise_arr[b] = red[w0] + red[w0 + 1] + red[w0 + 2] + red[w0 + 3];
        }
    }
}

// ---------------- kernel 2: class sums (no atomics) ----------------
__global__ void classsum_kernel(const int* __restrict__ labels) {
    int c = blockIdx.x;
    int t = threadIdx.x;
    float acc = 0.f;
    int cnt = 0;
    for (int b = 0; b < NBATCH; b++) {
        if (labels[b] == c) { acc += g_Bb[b * FD + t]; cnt++; }
    }
    g_F[c * FD + t] = acc;
    if (t == 0) g_cnt[c] = cnt;
}

// ---------------- kernel 3: symmetric HMMA gram + two-sided LSE epilogue ----------------
#define SM_A_HI 0
#define SM_A_LO 32768
#define SM_B(buf, hl) (65536 + (buf) * 65536 + (hl) * 32768)
#define SM_ROWRED 196608
#define SMEM_BYTES (200704 + 1024)

__global__ void __launch_bounds__(512, 1) gram_kernel() {
    extern __shared__ char smraw[];
    uint32_t su = smem_u32(smraw);
    uint32_t base = (su + 1023u) & ~1023u;

    int tid = threadIdx.x;
    int l = tid & 31;
    int wid = tid >> 5;
    int wx = wid & 3, wy = wid >> 2;
    int mb = wy * 32, nb = wx * 32;

    // ---- tile range (triangular flat index over 2080 tiles, 148 CTAs) ----
    int cta = blockIdx.x;
    int t0 = cta * 14 + (cta < 8 ? cta : 8);
    int cnt = 14 + (cta < 8 ? 1 : 0);
    int rb = 0, off = 0;
    while (t0 >= off + (64 - rb)) { off += 64 - rb; rb++; }
    int cb = rb + (t0 - off);
    int a_rb = rb;
    int c0run = cb;

    // ---- prologue: A(rb) + B(cb)->buf0 ----
#pragma unroll
    for (int k = 0; k < 4; k++) {
        int ch = tid * 4 + k;
        cp16(base + SM_A_HI + ch * 16, g_fhi_sw + rb * 2048 + ch);
        cp16(base + SM_A_LO + ch * 16, g_flo_sw + rb * 2048 + ch);
        cp16(base + SM_B(0, 0) + ch * 16, g_fhi_sw + cb * 2048 + ch);
        cp16(base + SM_B(0, 1) + ch * 16, g_flo_sw + cb * 2048 + ch);
    }
    CP_COMMIT();

    // ---- lane addressing ----
    int rowA = l & 15;
    int cA = l >> 4;
    int xA = rowA & 7;
    int rowB = (l & 7) + ((l >> 4) << 3);
    int cB = (l >> 3) & 1;
    int xB = rowB & 7;
    uint32_t aHi = base + SM_A_HI + (mb + rowA) * 256;
    uint32_t aLo = base + SM_A_LO + (mb + rowA) * 256;

    float m[4], lv[4];
#pragma unroll
    for (int s = 0; s < 4; s++) { m[s] = -1.0e30f; lv[s] = 0.f; }

    for (int i = 0; i < cnt; i++) {
        int b = i & 1;
        bool has_next = (i + 1 < cnt);
        int rbn = rb, cbn = cb + 1;
        if (cb == 63) { rbn = rb + 1; cbn = rb + 1; }

        __syncthreads();   // prev tile fully consumed: buf b^1 free

        if (a_rb != rb) {  // run boundary: reload A (rare)
#pragma unroll
            for (int k = 0; k < 4; k++) {
                int ch = tid * 4 + k;
                cp16(base + SM_A_HI + ch * 16, g_fhi_sw + rb * 2048 + ch);
                cp16(base + SM_A_LO + ch * 16, g_flo_sw + rb * 2048 + ch);
            }
            CP_COMMIT();
            CP_WAIT0();
            a_rb = rb;
        }
        if (has_next) {
            uint32_t dh = base + SM_B(b ^ 1, 0);
            uint32_t dl = base + SM_B(b ^ 1, 1);
#pragma unroll
            for (int k = 0; k < 4; k++) {
                int ch = tid * 4 + k;
                cp16(dh + ch * 16, g_fhi_sw + cbn * 2048 + ch);
                cp16(dl + ch * 16, g_flo_sw + cbn * 2048 + ch);
            }
        }
        CP_COMMIT();
        CP_WAIT1();
        __syncthreads();   // tile's B visible

        // ---- MMA: 3-pass hi/lo split, pass-major order (dep distance 8) ----
        float acc[2][4][4];
#pragma unroll
        for (int mf = 0; mf < 2; mf++)
#pragma unroll
            for (int nf = 0; nf < 4; nf++)
#pragma unroll
                for (int r = 0; r < 4; r++) acc[mf][nf][r] = 0.f;

        uint32_t bHi = base + SM_B(b, 0) + (nb + rowB) * 256;
        uint32_t bLo = base + SM_B(b, 1) + (nb + rowB) * 256;

#pragma unroll
        for (int s = 0; s < 8; s++) {
            uint32_t offA = (uint32_t)(((2 * s + cA) ^ xA) << 4);
            uint32_t offB = (uint32_t)(((2 * s + cB) ^ xB) << 4);
            uint32_t ah[8], al[8], bh[8], bl[8];
            LDSM4(&ah[0], aHi + offA);
            LDSM4(&ah[4], aHi + 4096 + offA);
            LDSM4(&al[0], aLo + offA);
            LDSM4(&al[4], aLo + 4096 + offA);
            LDSM4(&bh[0], bHi + offB);
            LDSM4(&bh[4], bHi + 4096 + offB);
            LDSM4(&bl[0], bLo + offB);
            LDSM4(&bl[4], bLo + 4096 + offB);
#pragma unroll
            for (int mf = 0; mf < 2; mf++)
#pragma unroll
                for (int nf = 0; nf < 4; nf++)
                    MMA(acc[mf][nf], &ah[4 * mf], bh[2 * nf], bh[2 * nf + 1]);
#pragma unroll
            for (int mf = 0; mf < 2; mf++)
#pragma unroll
                for (int nf = 0; nf < 4; nf++)
                    MMA(acc[mf][nf], &ah[4 * mf], bl[2 * nf], bl[2 * nf + 1]);
#pragma unroll
            for (int mf = 0; mf < 2; mf++)
#pragma unroll
                for (int nf = 0; nf < 4; nf++)
                    MMA(acc[mf][nf], &al[4 * mf], bh[2 * nf], bh[2 * nf + 1]);
        }

        bool diag = (rb == cb);

        // ---- row-side online epilogue ----
        int cbb[4];
#pragma unroll
        for (int nf = 0; nf < 4; nf++)
            cbb[nf] = (cb * 128 + nb + nf * 8) >> 4;
        int rbid0 = (rb * 128 + mb) >> 4;

#pragma unroll
        for (int mf = 0; mf < 2; mf++) {
            int rbid = rbid0 + mf;
#pragma unroll
            for (int h = 0; h < 2; h++) {
                int slot = mf * 2 + h;
                float v[8];
                float vmax = -3.0e38f;
                if (diag) {
#pragma unroll
                    for (int nf = 0; nf < 4; nf++) {
                        bool msk = (rbid == cbb[nf]);
                        float x0 = msk ? -3.0e38f : acc[mf][nf][2 * h];
                        float x1 = msk ? -3.0e38f : acc[mf][nf][2 * h + 1];
                        v[2 * nf] = x0; v[2 * nf + 1] = x1;
                        vmax = fmaxf(vmax, fmaxf(x0, x1));
                    }
                } else {
#pragma unroll
                    for (int nf = 0; nf < 4; nf++) {
                        float x0 = acc[mf][nf][2 * h];
                        float x1 = acc[mf][nf][2 * h + 1];
                        v[2 * nf] = x0; v[2 * nf + 1] = x1;
                        vmax = fmaxf(vmax, fmaxf(x0, x1));
                    }
                }
                vmax = fmaxf(vmax, __shfl_xor_sync(0xffffffffu, vmax, 1));
                vmax = fmaxf(vmax, __shfl_xor_sync(0xffffffffu, vmax, 2));
                float newM = fmaxf(m[slot], vmax);
                float s = 0.f;
                if (vmax > newM - 6.2f) {
#pragma unroll
                    for (int j = 0; j < 8; j++)
                        if (v[j] > newM - 6.2f)
                            s += __expf((v[j] - newM) * INV_T);
                }
                s += __shfl_xor_sync(0xffffffffu, s, 1);
                s += __shfl_xor_sync(0xffffffffu, s, 2);
                if (newM > m[slot]) {
                    lv[slot] = lv[slot] * __expf((m[slot] - newM) * INV_T) + s;
                    m[slot] = newM;
                } else {
                    lv[slot] += s;
                }
            }
        }

        // ---- col-side epilogue: per-warp, straight to global slots ----
        if (!diag) {
            int colg = cb * 128 + nb;
            int sub_ix = rb * 4 + wy;
#pragma unroll
            for (int nf = 0; nf < 4; nf++) {
#pragma unroll
                for (int par = 0; par < 2; par++) {
                    float a0 = acc[0][nf][par],     a1 = acc[0][nf][2 + par];
                    float b0 = acc[1][nf][par],     b1 = acc[1][nf][2 + par];
                    float mx = fmaxf(fmaxf(a0, a1), fmaxf(b0, b1));
                    mx = fmaxf(mx, __shfl_xor_sync(0xffffffffu, mx, 4));
                    mx = fmaxf(mx, __shfl_xor_sync(0xffffffffu, mx, 8));
                    mx = fmaxf(mx, __shfl_xor_sync(0xffffffffu, mx, 16));
                    float s = 0.f;
                    if (a0 > mx - 6.2f) s += __expf((a0 - mx) * INV_T);
                    if (a1 > mx - 6.2f) s += __expf((a1 - mx) * INV_T);
                    if (b0 > mx - 6.2f) s += __expf((b0 - mx) * INV_T);
                    if (b1 > mx - 6.2f) s += __expf((b1 - mx) * INV_T);
                    s += __shfl_xor_sync(0xffffffffu, s, 4);
                    s += __shfl_xor_sync(0xffffffffu, s, 8);
                    s += __shfl_xor_sync(0xffffffffu, s, 16);
                    if (l < 4)
                        g_slot[(size_t)(colg + nf * 8 + 2 * l + par) * 256 + sub_ix] =
                            make_float2(mx, s);
                }
            }
        }

        // ---- row-side flush at run end (rare) ----
        bool runend = !has_next || (rbn != rb);
        if (runend) {
            float2* rowred = (float2*)(smraw + (base - su) + SM_ROWRED);
            __syncthreads();
            if ((l & 3) == 0) {
                int g = l >> 2;
#pragma unroll
                for (int mf = 0; mf < 2; mf++)
#pragma unroll
                    for (int h = 0; h < 2; h++) {
                        int slot = mf * 2 + h;
                        rowred[(mb + mf * 16 + 8 * h + g) * 4 + wx] =
                            make_float2(m[slot], lv[slot]);
                    }
            }
            __syncthreads();
            if (tid < 128) {
                float2 p0 = rowred[tid * 4 + 0], p1 = rowred[tid * 4 + 1];
                float2 p2 = rowred[tid * 4 + 2], p3 = rowred[tid * 4 + 3];
                float M = fmaxf(fmaxf(p0.x, p1.x), fmaxf(p2.x, p3.x));
                float L = p0.y * __expf((p0.x - M) * INV_T)
                        + p1.y * __expf((p1.x - M) * INV_T)
                        + p2.y * __expf((p2.x - M) * INV_T)
                        + p3.y * __expf((p3.x - M) * INV_T);
                g_slot[(size_t)(rb * 128 + tid) * 256 + c0run * 4] = make_float2(M, L);
            }
#pragma unroll
            for (int s = 0; s < 4; s++) { m[s] = -1.0e30f; lv[s] = 0.f; }
            c0run = cbn;
        }
        rb = rbn; cb = cbn;
    }
}

// ---------------- kernel 4: slot merge + per-row class-loss term (warp per row) ----------------
__global__ void finish_kernel(const float* __restrict__ f,
                              const int* __restrict__ labels) {
    int i = (blockIdx.x * blockDim.x + threadIdx.x) >> 5;
    int lane = threadIdx.x & 31;
    int b = i >> 4;
    int lab = labels[b];

    const float4* sp = (const float4*)(g_slot + (size_t)i * 256 + lane * 8);
    float4 q0 = sp[0], q1 = sp[1], q2 = sp[2], q3 = sp[3];
    float2 s[8];
    s[0] = make_float2(q0.x, q0.y); s[1] = make_float2(q0.z, q0.w);
    s[2] = make_float2(q1.x, q1.y); s[3] = make_float2(q1.z, q1.w);
    s[4] = make_float2(q2.x, q2.y); s[5] = make_float2(q2.z, q2.w);
    s[6] = make_float2(q3.x, q3.y); s[7] = make_float2(q3.z, q3.w);
    float M = s[0].x;
#pragma unroll
    for (int k = 1; k < 8; k++) M = fmaxf(M, s[k].x);
#pragma unroll
    for (int sh = 16; sh > 0; sh >>= 1)
        M = fmaxf(M, __shfl_xor_sync(0xffffffffu, M, sh));
    float L = 0.f;
#pragma unroll
    for (int k = 0; k < 8; k++)
        if (s[k].x > M - 6.2f) L += s[k].y * __expf((s[k].x - M) * INV_T);
#pragma unroll
    for (int sh = 16; sh > 0; sh >>= 1)
        L += __shfl_xor_sync(0xffffffffu, L, sh);

    // closed-form positive sum
    float4 fv = ((const float4*)f)[i * 32 + lane];
    float4 Fv = ((const float4*)g_F)[lab * 32 + lane];
    float4 Bv = ((const float4*)g_Bb)[b * 32 + lane];
    float d = fv.x * (Fv.x - Bv.x) + fv.y * (Fv.y - Bv.y)
            + fv.z * (Fv.z - Bv.z) + fv.w * (Fv.w - Bv.w);
#pragma unroll
    for (int sh = 16; sh > 0; sh >>= 1)
        d += __shfl_xor_sync(0xffffffffu, d, sh);

    __shared__ float wterm[8];
    if (lane == 0) {
        float lse = M * INV_T + logf(L);
        float P = (float)(g_cnt[lab] * 16 - 16);
        float term = (P > 0.f) ? -(d * INV_T - P * lse) / (P + 1e-8f) : 0.f;
        wterm[threadIdx.x >> 5] = term;
    }
    __syncthreads();
    if (threadIdx.x == 0) {
        float ssum = 0.f;
#pragma unroll
        for (int w = 0; w < 8; w++) ssum += wterm[w];
        g_class_arr[blockIdx.x] = ssum;
    }
}

// ---------------- kernel 5: final scalar ----------------
__global__ void final_kernel(float* __restrict__ out) {
    __shared__ double shc[256], shn[256];
    int t = threadIdx.x;
    double c = 0.0, n = 0.0;
    for (int i = t; i < 1024; i += 256) c += (double)g_class_arr[i];
    for (int i = t; i < NBATCH; i += 256) n += (double)g_noise_arr[i];
    shc[t] = c; shn[t] = n;
    __syncthreads();
    for (int s = 128; s > 0; s >>= 1) {
        if (t < s) { shc[t] += shc[t + s]; shn[t] += shn[t + s]; }
        __syncthreads();
    }
    if (t == 0) {
        double loss_class = shc[0] / (double)N_ROWS;
        double s_noise_logits = shn[0] * (double)INV_T;
        double loss_noise = -(s_noise_logits / ((double)N_ROWS * 7.0)) / 0.07;
        double a = 1.0 / 3.0;
        out[0] = (float)(a * loss_class + a * loss_noise);
    }
}

// ---------------- launch ----------------
extern "C" void kernel_launch(void* const* d_in, const int* in_sizes, int n_in,
                              void* d_out, int out_size) {
    const float* f = (const float*)d_in[0];
    const int* labels = (const int*)d_in[1];
    float* out = (float*)d_out;

    cudaFuncSetAttribute(gram_kernel, cudaFuncAttributeMaxDynamicSharedMemorySize, SMEM_BYTES);

    setup_kernel<<<1792, 256>>>(f, labels);
    classsum_kernel<<<NCLASS, 128>>>(labels);
    gram_kernel<<<148, 512, SMEM_BYTES>>>();
    finish_kernel<<<1024, 256>>>(f, labels);
    final_kernel<<<1, 256>>>(out);
}

// round 6
// speedup vs baseline: 1.3222x; 1.3222x over previous
#include <cuda_runtime.h>
#include <cuda_fp16.h>
#include <math.h>
#include <stdint.h>

#define N_ROWS 8192
#define FD 128
#define INV_T 14.2857142857142857f   // 1/0.07
#define NBATCH 512
#define NCLASS 16

// ---------------- device-global scratch ----------------
__device__ uint4  g_f_sw[N_ROWS * 16];   // pre-swizzled fp16 features
__device__ float  g_F[NCLASS * FD];
__device__ int    g_cnt[NCLASS];
__device__ float  g_Bb[NBATCH * FD];
__device__ __align__(16) float2 g_slot[N_ROWS * 64];  // per-(row, block) LSE partials
__device__ float  g_noise_arr[NBATCH];
__device__ float  g_class_arr[1024];

// ---------------- helpers ----------------
__device__ __forceinline__ uint32_t smem_u32(const void* p) {
    uint32_t a;
    asm("{ .reg .u64 t; cvta.to.shared.u64 t, %1; cvt.u32.u64 %0, t; }" : "=r"(a) : "l"(p));
    return a;
}
__device__ __forceinline__ void cp16(uint32_t s, const void* g) {
    asm volatile("cp.async.cg.shared.global [%0], [%1], 16;" :: "r"(s), "l"(g) : "memory");
}
#define CP_COMMIT() asm volatile("cp.async.commit_group;" ::: "memory")
#define CP_WAIT1()  asm volatile("cp.async.wait_group 1;" ::: "memory")
#define CP_WAIT0()  asm volatile("cp.async.wait_group 0;" ::: "memory")

#define LDSM4(R, addr) \
    asm volatile("ldmatrix.sync.aligned.m8n8.x4.shared.b16 {%0,%1,%2,%3}, [%4];" \
        : "=r"((R)[0]), "=r"((R)[1]), "=r"((R)[2]), "=r"((R)[3]) : "r"(addr))

#define MMA(C, A, B0, B1) \
    asm volatile("mma.sync.aligned.m16n8k16.row.col.f32.f16.f16.f32 " \
        "{%0,%1,%2,%3}, {%4,%5,%6,%7}, {%8,%9}, {%0,%1,%2,%3};" \
        : "+f"((C)[0]), "+f"((C)[1]), "+f"((C)[2]), "+f"((C)[3]) \
        : "r"((A)[0]), "r"((A)[1]), "r"((A)[2]), "r"((A)[3]), "r"(B0), "r"(B1))

__device__ __forceinline__ uint32_t pack_h2(__half a, __half b) {
    __half2 t(a, b);
    return *reinterpret_cast<uint32_t*>(&t);
}

// ---------------- kernel 1: fused setup ----------------
// blocks [0,256): init slot table; [256,768): fp16 prep; [768,1024): batch sums + noise
__global__ void setup_kernel(const float* __restrict__ f, const int* __restrict__ labels) {
    __shared__ float red[8];
    int blk = blockIdx.x;
    int t = threadIdx.x;
    if (blk < 256) {
        float4* p = (float4*)g_slot;
        int base = (blk * 256 + t) * 4;
        float4 z = make_float4(-1.0e30f, 0.f, -1.0e30f, 0.f);
#pragma unroll
        for (int k = 0; k < 4; k++) p[base + k] = z;
    } else if (blk < 768) {
        int idx = (blk - 256) * 256 + t;   // 0..131071, one 16B chunk
        int row = idx >> 4;
        int c = idx & 15;
        float4 v0 = ((const float4*)f)[row * 32 + c * 2];
        float4 v1 = ((const float4*)f)[row * 32 + c * 2 + 1];
        uint32_t h[4];
        h[0] = pack_h2(__float2half_rn(v0.x), __float2half_rn(v0.y));
        h[1] = pack_h2(__float2half_rn(v0.z), __float2half_rn(v0.w));
        h[2] = pack_h2(__float2half_rn(v1.x), __float2half_rn(v1.y));
        h[3] = pack_h2(__float2half_rn(v1.z), __float2half_rn(v1.w));
        int dst = ((row >> 7) << 11) + ((row & 127) << 4) + (c ^ (row & 7));
        g_f_sw[dst] = make_uint4(h[0], h[1], h[2], h[3]);
    } else {
        int b = (blk - 768) * 2 + (t >> 7);
        int tt = t & 127;
        float s16 = 0.f, s8a = 0.f, s8b = 0.f, ssq = 0.f;
#pragma unroll
        for (int r = 0; r < 16; r++) {
            float v = f[(b * 16 + r) * FD + tt];
            s16 += v;
            if (r < 8) s8a += v; else s8b += v;
            ssq += v * v;
        }
        g_Bb[b * FD + tt] = s16;
        float c = s8a * s8a + s8b * s8b - ssq;
#pragma unroll
        for (int sh = 16; sh > 0; sh >>= 1)
            c += __shfl_xor_sync(0xffffffffu, c, sh);
        if ((t & 31) == 0) red[t >> 5] = c;
        __syncthreads();
        if ((t & 127) == 0) {
            int w0 = t >> 5;   // 0 or 4
            g_noise_arr[b] = red[w0] + red[w0 + 1] + red[w0 + 2] + red[w0 + 3];
        }
    }
}

// ---------------- kernel 2: class sums (no atomics) ----------------
__global__ void classsum_kernel(const int* __restrict__ labels) {
    int c = blockIdx.x;
    int t = threadIdx.x;
    float acc = 0.f;
    int cnt = 0;
    for (int b = 0; b < NBATCH; b++) {
        if (labels[b] == c) { acc += g_Bb[b * FD + t]; cnt++; }
    }
    g_F[c * FD + t] = acc;
    if (t == 0) g_cnt[c] = cnt;
}

// ---------------- kernel 3: symmetric fp16 HMMA gram + two-sided LSE epilogue ----------------
#define SM_A 0
#define SM_B(buf) (32768 + (buf) * 32768)
#define SM_COLRED 98304
#define SM_ROWRED 102400
#define SMEM_BYTES (106496 + 1024)

__global__ void __launch_bounds__(512, 1) gram_kernel() {
    extern __shared__ char smraw[];
    uint32_t su = smem_u32(smraw);
    uint32_t base = (su + 1023u) & ~1023u;

    int tid = threadIdx.x;
    int l = tid & 31;
    int wid = tid >> 5;
    int wx = wid & 3, wy = wid >> 2;
    int mb = wy * 32, nb = wx * 32;

    // ---- tile range (triangular flat index over 2080 tiles, 148 CTAs) ----
    int cta = blockIdx.x;
    int t0 = cta * 14 + (cta < 8 ? cta : 8);
    int cnt = 14 + (cta < 8 ? 1 : 0);
    int rb = 0, off = 0;
    while (t0 >= off + (64 - rb)) { off += 64 - rb; rb++; }
    int cb = rb + (t0 - off);
    int a_rb = rb;
    int c0run = cb;

    // ---- prologue: A(rb) + B(cb)->buf0 ----
#pragma unroll
    for (int k = 0; k < 4; k++) {
        int ch = tid * 4 + k;
        cp16(base + SM_A + ch * 16, g_f_sw + rb * 2048 + ch);
        cp16(base + SM_B(0) + ch * 16, g_f_sw + cb * 2048 + ch);
    }
    CP_COMMIT();

    // ---- lane addressing ----
    int rowA = l & 15;
    int cA = l >> 4;
    int xA = rowA & 7;
    int rowB = (l & 7) + ((l >> 4) << 3);
    int cB = (l >> 3) & 1;
    int xB = rowB & 7;
    uint32_t aP = base + SM_A + (mb + rowA) * 256;

    float m[4], lv[4];
#pragma unroll
    for (int s = 0; s < 4; s++) { m[s] = -1.0e30f; lv[s] = 0.f; }

    for (int i = 0; i < cnt; i++) {
        int b = i & 1;
        bool has_next = (i + 1 < cnt);
        int rbn = rb, cbn = cb + 1;
        if (cb == 63) { rbn = rb + 1; cbn = rb + 1; }

        __syncthreads();   // prev tile fully consumed: buf b^1 free

        if (a_rb != rb) {  // run boundary: reload A (rare)
#pragma unroll
            for (int k = 0; k < 4; k++) {
                int ch = tid * 4 + k;
                cp16(base + SM_A + ch * 16, g_f_sw + rb * 2048 + ch);
            }
            CP_COMMIT();
            CP_WAIT0();
            a_rb = rb;
        }
        if (has_next) {
            uint32_t dB = base + SM_B(b ^ 1);
#pragma unroll
            for (int k = 0; k < 4; k++) {
                int ch = tid * 4 + k;
                cp16(dB + ch * 16, g_f_sw + cbn * 2048 + ch);
            }
        }
        CP_COMMIT();
        CP_WAIT1();        // this tile's B complete
        __syncthreads();

        // ---- single-pass fp16 MMA ----
        float acc[2][4][4];
#pragma unroll
        for (int mf = 0; mf < 2; mf++)
#pragma unroll
            for (int nf = 0; nf < 4; nf++)
#pragma unroll
                for (int r = 0; r < 4; r++) acc[mf][nf][r] = 0.f;

        uint32_t bP = base + SM_B(b) + (nb + rowB) * 256;

#pragma unroll
        for (int s = 0; s < 8; s++) {
            uint32_t offA = (uint32_t)(((2 * s + cA) ^ xA) << 4);
            uint32_t offB = (uint32_t)(((2 * s + cB) ^ xB) << 4);
            uint32_t ah[8], bh[8];
            LDSM4(&ah[0], aP + offA);
            LDSM4(&ah[4], aP + 4096 + offA);
            LDSM4(&bh[0], bP + offB);
            LDSM4(&bh[4], bP + 4096 + offB);
#pragma unroll
            for (int mf = 0; mf < 2; mf++)
#pragma unroll
                for (int nf = 0; nf < 4; nf++)
                    MMA(acc[mf][nf], &ah[4 * mf], bh[2 * nf], bh[2 * nf + 1]);
        }

        bool diag = (rb == cb);

        // ---- row-side online epilogue ----
        int cbb[4];
#pragma unroll
        for (int nf = 0; nf < 4; nf++)
            cbb[nf] = (cb * 128 + nb + nf * 8) >> 4;
        int rbid0 = (rb * 128 + mb) >> 4;

#pragma unroll
        for (int mf = 0; mf < 2; mf++) {
            int rbid = rbid0 + mf;
#pragma unroll
            for (int h = 0; h < 2; h++) {
                int slot = mf * 2 + h;
                float v[8];
                float vmax = -3.0e38f;
                if (diag) {
#pragma unroll
                    for (int nf = 0; nf < 4; nf++) {
                        bool msk = (rbid == cbb[nf]);
                        float x0 = msk ? -3.0e38f : acc[mf][nf][2 * h];
                        float x1 = msk ? -3.0e38f : acc[mf][nf][2 * h + 1];
                        v[2 * nf] = x0; v[2 * nf + 1] = x1;
                        vmax = fmaxf(vmax, fmaxf(x0, x1));
                    }
                } else {
#pragma unroll
                    for (int nf = 0; nf < 4; nf++) {
                        float x0 = acc[mf][nf][2 * h];
                        float x1 = acc[mf][nf][2 * h + 1];
                        v[2 * nf] = x0; v[2 * nf + 1] = x1;
                        vmax = fmaxf(vmax, fmaxf(x0, x1));
                    }
                }
                vmax = fmaxf(vmax, __shfl_xor_sync(0xffffffffu, vmax, 1));
                vmax = fmaxf(vmax, __shfl_xor_sync(0xffffffffu, vmax, 2));
                float newM = fmaxf(m[slot], vmax);
                float s = 0.f;
                if (vmax > newM - 6.2f) {
#pragma unroll
                    for (int j = 0; j < 8; j++)
                        if (v[j] > newM - 6.2f)
                            s += __expf((v[j] - newM) * INV_T);
                }
                s += __shfl_xor_sync(0xffffffffu, s, 1);
                s += __shfl_xor_sync(0xffffffffu, s, 2);
                if (newM > m[slot]) {
                    lv[slot] = lv[slot] * __expf((m[slot] - newM) * INV_T) + s;
                    m[slot] = newM;
                } else {
                    lv[slot] += s;
                }
            }
        }

        // ---- col-side epilogue (off-diagonal only; smem merge) ----
        if (!diag) {
            float2* colred = (float2*)(smraw + (base - su) + SM_COLRED);
            float cm[8], cs[8];
#pragma unroll
            for (int nf = 0; nf < 4; nf++)
#pragma unroll
                for (int par = 0; par < 2; par++) {
                    int ix = nf * 2 + par;
                    float a0 = acc[0][nf][par],     a1 = acc[0][nf][2 + par];
                    float b0 = acc[1][nf][par],     b1 = acc[1][nf][2 + par];
                    float mx = fmaxf(fmaxf(a0, a1), fmaxf(b0, b1));
                    mx = fmaxf(mx, __shfl_xor_sync(0xffffffffu, mx, 4));
                    mx = fmaxf(mx, __shfl_xor_sync(0xffffffffu, mx, 8));
                    mx = fmaxf(mx, __shfl_xor_sync(0xffffffffu, mx, 16));
                    float s = 0.f;
                    if (a0 > mx - 6.2f) s += __expf((a0 - mx) * INV_T);
                    if (a1 > mx - 6.2f) s += __expf((a1 - mx) * INV_T);
                    if (b0 > mx - 6.2f) s += __expf((b0 - mx) * INV_T);
                    if (b1 > mx - 6.2f) s += __expf((b1 - mx) * INV_T);
                    s += __shfl_xor_sync(0xffffffffu, s, 4);
                    s += __shfl_xor_sync(0xffffffffu, s, 8);
                    s += __shfl_xor_sync(0xffffffffu, s, 16);
                    cm[ix] = mx; cs[ix] = s;
                }
            if (l < 4) {
#pragma unroll
                for (int nf = 0; nf < 4; nf++)
#pragma unroll
                    for (int par = 0; par < 2; par++)
                        colred[wy * 128 + nb + nf * 8 + 2 * l + par] =
                            make_float2(cm[nf * 2 + par], cs[nf * 2 + par]);
            }
            __syncthreads();
            if (tid < 128) {
                float2 p0 = colred[tid], p1 = colred[128 + tid];
                float2 p2 = colred[256 + tid], p3 = colred[384 + tid];
                float M = fmaxf(fmaxf(p0.x, p1.x), fmaxf(p2.x, p3.x));
                float L = p0.y * __expf((p0.x - M) * INV_T)
                        + p1.y * __expf((p1.x - M) * INV_T)
                        + p2.y * __expf((p2.x - M) * INV_T)
                        + p3.y * __expf((p3.x - M) * INV_T);
                g_slot[(size_t)(cb * 128 + tid) * 64 + rb] = make_float2(M, L);
            }
        }

        // ---- row-side flush at run end (rare) ----
        bool runend = !has_next || (rbn != rb);
        if (runend) {
            float2* rowred = (float2*)(smraw + (base - su) + SM_ROWRED);
            __syncthreads();
            if ((l & 3) == 0) {
                int g = l >> 2;
#pragma unroll
                for (int mf = 0; mf < 2; mf++)
#pragma unroll
                    for (int h = 0; h < 2; h++) {
                        int slot = mf * 2 + h;
                        rowred[(mb + mf * 16 + 8 * h + g) * 4 + wx] =
                            make_float2(m[slot], lv[slot]);
                    }
            }
            __syncthreads();
            if (tid < 128) {
                float2 p0 = rowred[tid * 4 + 0], p1 = rowred[tid * 4 + 1];
                float2 p2 = rowred[tid * 4 + 2], p3 = rowred[tid * 4 + 3];
                float M = fmaxf(fmaxf(p0.x, p1.x), fmaxf(p2.x, p3.x));
                float L = p0.y * __expf((p0.x - M) * INV_T)
                        + p1.y * __expf((p1.x - M) * INV_T)
                        + p2.y * __expf((p2.x - M) * INV_T)
                        + p3.y * __expf((p3.x - M) * INV_T);
                g_slot[(size_t)(rb * 128 + tid) * 64 + c0run] = make_float2(M, L);
            }
#pragma unroll
            for (int s = 0; s < 4; s++) { m[s] = -1.0e30f; lv[s] = 0.f; }
            c0run = cbn;
        }
        rb = rbn; cb = cbn;
    }
}

// ---------------- kernel 4: slot merge + per-row class-loss term (warp per row) ----------------
__global__ void finish_kernel(const float* __restrict__ f,
                              const int* __restrict__ labels) {
    int i = (blockIdx.x * blockDim.x + threadIdx.x) >> 5;
    int lane = threadIdx.x & 31;
    int b = i >> 4;
    int lab = labels[b];

    // merge 64 slots (2 per lane, then 5-level butterfly)
    float4 q = ((const float4*)(g_slot + (size_t)i * 64))[lane];
    float2 s0 = make_float2(q.x, q.y), s1 = make_float2(q.z, q.w);
    float M = fmaxf(s0.x, s1.x);
    float L = s0.y * __expf((s0.x - M) * INV_T) + s1.y * __expf((s1.x - M) * INV_T);
#pragma unroll
    for (int sh = 16; sh > 0; sh >>= 1) {
        float Mo = __shfl_xor_sync(0xffffffffu, M, sh);
        float Lo = __shfl_xor_sync(0xffffffffu, L, sh);
        float Mn = fmaxf(M, Mo);
        L = L * __expf((M - Mn) * INV_T) + Lo * __expf((Mo - Mn) * INV_T);
        M = Mn;
    }

    // closed-form positive sum
    float4 fv = ((const float4*)f)[i * 32 + lane];
    float4 Fv = ((const float4*)g_F)[lab * 32 + lane];
    float4 Bv = ((const float4*)g_Bb)[b * 32 + lane];
    float d = fv.x * (Fv.x - Bv.x) + fv.y * (Fv.y - Bv.y)
            + fv.z * (Fv.z - Bv.z) + fv.w * (Fv.w - Bv.w);
#pragma unroll
    for (int sh = 16; sh > 0; sh >>= 1)
        d += __shfl_xor_sync(0xffffffffu, d, sh);

    __shared__ float wterm[8];
    if (lane == 0) {
        float lse = M * INV_T + logf(L);
        float P = (float)(g_cnt[lab] * 16 - 16);
        float term = (P > 0.f) ? -(d * INV_T - P * lse) / (P + 1e-8f) : 0.f;
        wterm[threadIdx.x >> 5] = term;
    }
    __syncthreads();
    if (threadIdx.x == 0) {
        float ssum = 0.f;
#pragma unroll
        for (int w = 0; w < 8; w++) ssum += wterm[w];
        g_class_arr[blockIdx.x] = ssum;
    }
}

// ---------------- kernel 5: final scalar ----------------
__global__ void final_kernel(float* __restrict__ out) {
    __shared__ double shc[256], shn[256];
    int t = threadIdx.x;
    double c = 0.0, n = 0.0;
    for (int i = t; i < 1024; i += 256) c += (double)g_class_arr[i];
    for (int i = t; i < NBATCH; i += 256) n += (double)g_noise_arr[i];
    shc[t] = c; shn[t] = n;
    __syncthreads();
    for (int s = 128; s > 0; s >>= 1) {
        if (t < s) { shc[t] += shc[t + s]; shn[t] += shn[t + s]; }
        __syncthreads();
    }
    if (t == 0) {
        double loss_class = shc[0] / (double)N_ROWS;
        double s_noise_logits = shn[0] * (double)INV_T;
        double loss_noise = -(s_noise_logits / ((double)N_ROWS * 7.0)) / 0.07;
        double a = 1.0 / 3.0;
        out[0] = (float)(a * loss_class + a * loss_noise);
    }
}

// ---------------- launch ----------------
extern "C" void kernel_launch(void* const* d_in, const int* in_sizes, int n_in,
                              void* d_out, int out_size) {
    const float* f = (const float*)d_in[0];
    const int* labels = (const int*)d_in[1];
    float* out = (float*)d_out;

    cudaFuncSetAttribute(gram_kernel, cudaFuncAttributeMaxDynamicSharedMemorySize, SMEM_BYTES);

    setup_kernel<<<1024, 256>>>(f, labels);
    classsum_kernel<<<NCLASS, 128>>>(labels);
    gram_kernel<<<148, 512, SMEM_BYTES>>>();
    finish_kernel<<<1024, 256>>>(f, labels);
    final_kernel<<<1, 256>>>(out);
}

// round 7
// speedup vs baseline: 1.6834x; 1.2733x over previous
#include <cuda_runtime.h>
#include <cuda_fp16.h>
#include <math.h>
#include <stdint.h>

#define N_ROWS 8192
#define FD 128
#define INV_T 14.2857142857142857f   // 1/0.07
#define NBATCH 512
#define NCLASS 16

// ---------------- device-global scratch ----------------
__device__ uint4  g_f_sw[N_ROWS * 16];   // pre-swizzled fp16 features (tile-contiguous)
__device__ float  g_F[NCLASS * FD];
__device__ int    g_cnt[NCLASS];
__device__ float  g_Bb[NBATCH * FD];
__device__ __align__(16) float2 g_slot[N_ROWS * 64];  // per-(row, block) LSE partials
__device__ float  g_noise_arr[NBATCH];
__device__ float  g_class_arr[1024];

// ---------------- helpers ----------------
__device__ __forceinline__ uint32_t smem_u32(const void* p) {
    uint32_t a;
    asm("{ .reg .u64 t; cvta.to.shared.u64 t, %1; cvt.u32.u64 %0, t; }" : "=r"(a) : "l"(p));
    return a;
}
#define MBAR_INIT(bar, cnt) \
    asm volatile("mbarrier.init.shared.b64 [%0], %1;" :: "r"(bar), "r"(cnt) : "memory")
#define MBAR_EXPECT_TX(bar, bytes) \
    asm volatile("mbarrier.arrive.expect_tx.shared.b64 _, [%0], %1;" :: "r"(bar), "r"(bytes) : "memory")
#define BULK_G2S(dst, src, bytes, bar) \
    asm volatile("cp.async.bulk.shared::cluster.global.mbarrier::complete_tx::bytes [%0], [%1], %2, [%3];" \
                 :: "r"(dst), "l"(src), "r"(bytes), "r"(bar) : "memory")
#define FENCE_PROXY_ASYNC() asm volatile("fence.proxy.async.shared::cta;" ::: "memory")
#define MBAR_WAIT(bar, parity) do { \
    uint32_t _m = (bar); uint32_t _p = (parity); uint32_t _d; \
    asm volatile("{ .reg .pred p; mbarrier.try_wait.parity.acquire.cta.shared::cta.b64 p, [%1], %2; selp.b32 %0, 1, 0, p; }" \
                 : "=r"(_d) : "r"(_m), "r"(_p) : "memory"); \
    if (!_d) { \
        asm volatile("{ .reg .pred P1; WL_%=: mbarrier.try_wait.parity.acquire.cta.shared::cta.b64 P1, [%0], %1, 0x989680; @P1 bra.uni WD_%=; bra.uni WL_%=; WD_%=: }" \
                     :: "r"(_m), "r"(_p) : "memory"); \
    } } while (0)

#define LDSM4(R, addr) \
    asm volatile("ldmatrix.sync.aligned.m8n8.x4.shared.b16 {%0,%1,%2,%3}, [%4];" \
        : "=r"((R)[0]), "=r"((R)[1]), "=r"((R)[2]), "=r"((R)[3]) : "r"(addr))

#define MMA(C, A, B0, B1) \
    asm volatile("mma.sync.aligned.m16n8k16.row.col.f32.f16.f16.f32 " \
        "{%0,%1,%2,%3}, {%4,%5,%6,%7}, {%8,%9}, {%0,%1,%2,%3};" \
        : "+f"((C)[0]), "+f"((C)[1]), "+f"((C)[2]), "+f"((C)[3]) \
        : "r"((A)[0]), "r"((A)[1]), "r"((A)[2]), "r"((A)[3]), "r"(B0), "r"(B1))

__device__ __forceinline__ uint32_t pack_h2(__half a, __half b) {
    __half2 t(a, b);
    return *reinterpret_cast<uint32_t*>(&t);
}

// ---------------- kernel 1: fused setup ----------------
// blocks [0,256): slot init (+blk0 zeros g_F/g_cnt); [256,768): fp16 prep; [768,1024): batch sums + noise
__global__ void setup_kernel(const float* __restrict__ f, const int* __restrict__ labels) {
    __shared__ float red[8];
    int blk = blockIdx.x;
    int t = threadIdx.x;
    if (blk < 256) {
        float4* p = (float4*)g_slot;
        int base = (blk * 256 + t) * 4;
        float4 z = make_float4(-1.0e30f, 0.f, -1.0e30f, 0.f);
#pragma unroll
        for (int k = 0; k < 4; k++) p[base + k] = z;
        if (blk == 0) {
#pragma unroll
            for (int k = 0; k < 8; k++) g_F[t + 256 * k] = 0.f;
            if (t < NCLASS) g_cnt[t] = 0;
        }
    } else if (blk < 768) {
        int idx = (blk - 256) * 256 + t;   // 0..131071, one 16B chunk
        int row = idx >> 4;
        int c = idx & 15;
        float4 v0 = ((const float4*)f)[row * 32 + c * 2];
        float4 v1 = ((const float4*)f)[row * 32 + c * 2 + 1];
        uint32_t h[4];
        h[0] = pack_h2(__float2half_rn(v0.x), __float2half_rn(v0.y));
        h[1] = pack_h2(__float2half_rn(v0.z), __float2half_rn(v0.w));
        h[2] = pack_h2(__float2half_rn(v1.x), __float2half_rn(v1.y));
        h[3] = pack_h2(__float2half_rn(v1.z), __float2half_rn(v1.w));
        int dst = ((row >> 7) << 11) + ((row & 127) << 4) + (c ^ (row & 7));
        g_f_sw[dst] = make_uint4(h[0], h[1], h[2], h[3]);
    } else {
        int b = (blk - 768) * 2 + (t >> 7);
        int tt = t & 127;
        float s16 = 0.f, s8a = 0.f, s8b = 0.f, ssq = 0.f;
#pragma unroll
        for (int r = 0; r < 16; r++) {
            float v = f[(b * 16 + r) * FD + tt];
            s16 += v;
            if (r < 8) s8a += v; else s8b += v;
            ssq += v * v;
        }
        g_Bb[b * FD + tt] = s16;
        float c = s8a * s8a + s8b * s8b - ssq;
#pragma unroll
        for (int sh = 16; sh > 0; sh >>= 1)
            c += __shfl_xor_sync(0xffffffffu, c, sh);
        if ((t & 31) == 0) red[t >> 5] = c;
        __syncthreads();
        if ((t & 127) == 0) {
            int w0 = t >> 5;   // 0 or 4
            g_noise_arr[b] = red[w0] + red[w0 + 1] + red[w0 + 2] + red[w0 + 3];
        }
    }
}

// ---------------- kernel 2: class sums (atomic scatter, one block per batch) ----------------
__global__ void classsum_kernel(const int* __restrict__ labels) {
    int b = blockIdx.x;
    int t = threadIdx.x;
    int lab = labels[b];
    atomicAdd(&g_F[lab * FD + t], g_Bb[b * FD + t]);
    if (t == 0) atomicAdd(&g_cnt[lab], 1);
}

// ---------------- kernel 3: symmetric fp16 HMMA gram + two-sided LSE epilogue ----------------
#define SM_A 0
#define SM_B(buf) (32768 + (buf) * 32768)
#define SM_COLRED 98304
#define SM_ROWRED 102400
#define SM_BARS 106496
#define SMEM_BYTES (106624 + 1024)
#define TILE_BYTES 32768u

__global__ void __launch_bounds__(512, 1) gram_kernel() {
    extern __shared__ char smraw[];
    uint32_t su = smem_u32(smraw);
    uint32_t base = (su + 1023u) & ~1023u;

    int tid = threadIdx.x;
    int l = tid & 31;
    int wid = tid >> 5;
    int wx = wid & 3, wy = wid >> 2;
    int mb = wy * 32, nb = wx * 32;

    uint32_t barA = base + SM_BARS;
    uint32_t barB0 = base + SM_BARS + 8;
    uint32_t barB1 = base + SM_BARS + 16;

    // ---- tile range (triangular flat index over 2080 tiles, 148 CTAs) ----
    int cta = blockIdx.x;
    int t0 = cta * 14 + (cta < 8 ? cta : 8);
    int cnt = 14 + (cta < 8 ? 1 : 0);
    int rb = 0, off = 0;
    while (t0 >= off + (64 - rb)) { off += 64 - rb; rb++; }
    int cb = rb + (t0 - off);
    int c0run = cb;

    // ---- barriers + prologue bulk copies ----
    if (tid == 0) {
        MBAR_INIT(barA, 1);
        MBAR_INIT(barB0, 1);
        MBAR_INIT(barB1, 1);
        FENCE_PROXY_ASYNC();
    }
    __syncthreads();
    if (tid == 0) {
        MBAR_EXPECT_TX(barA, TILE_BYTES);
        BULK_G2S(base + SM_A, (const void*)(g_f_sw + rb * 2048), TILE_BYTES, barA);
        MBAR_EXPECT_TX(barB0, TILE_BYTES);
        BULK_G2S(base + SM_B(0), (const void*)(g_f_sw + cb * 2048), TILE_BYTES, barB0);
    }

    int a_cur = rb;
    int aPar = 0;
    bool a_ready = false;
    int bPar[2] = { 0, 0 };

    // ---- lane addressing ----
    int rowA = l & 15;
    int cA = l >> 4;
    int xA = rowA & 7;
    int rowB = (l & 7) + ((l >> 4) << 3);
    int cB = (l >> 3) & 1;
    int xB = rowB & 7;
    uint32_t aP = base + SM_A + (mb + rowA) * 256;

    float m[4], lv[4];
#pragma unroll
    for (int s = 0; s < 4; s++) { m[s] = -1.0e30f; lv[s] = 0.f; }

    for (int i = 0; i < cnt; i++) {
        int b = i & 1;
        bool has_next = (i + 1 < cnt);
        int rbn = rb, cbn = cb + 1;
        if (cb == 63) { rbn = rb + 1; cbn = rb + 1; }

        __syncthreads();   // prev tile fully consumed: buf b^1 / A / red areas free

        bool need_a = (rb != a_cur);
        if (tid == 0) {
            if (need_a) {
                MBAR_EXPECT_TX(barA, TILE_BYTES);
                BULK_G2S(base + SM_A, (const void*)(g_f_sw + rb * 2048), TILE_BYTES, barA);
            }
            if (has_next) {
                uint32_t barN = (b ^ 1) ? barB1 : barB0;
                MBAR_EXPECT_TX(barN, TILE_BYTES);
                BULK_G2S(base + SM_B(b ^ 1), (const void*)(g_f_sw + cbn * 2048), TILE_BYTES, barN);
            }
        }
        if (need_a) { a_cur = rb; a_ready = false; }
        if (!a_ready) { MBAR_WAIT(barA, aPar); aPar ^= 1; a_ready = true; }
        {
            uint32_t barC = b ? barB1 : barB0;
            MBAR_WAIT(barC, bPar[b]);
            bPar[b] ^= 1;
        }

        // ---- single-pass fp16 MMA ----
        float acc[2][4][4];
#pragma unroll
        for (int mf = 0; mf < 2; mf++)
#pragma unroll
            for (int nf = 0; nf < 4; nf++)
#pragma unroll
                for (int r = 0; r < 4; r++) acc[mf][nf][r] = 0.f;

        uint32_t bP = base + SM_B(b) + (nb + rowB) * 256;

#pragma unroll
        for (int s = 0; s < 8; s++) {
            uint32_t offA = (uint32_t)(((2 * s + cA) ^ xA) << 4);
            uint32_t offB = (uint32_t)(((2 * s + cB) ^ xB) << 4);
            uint32_t ah[8], bh[8];
            LDSM4(&ah[0], aP + offA);
            LDSM4(&ah[4], aP + 4096 + offA);
            LDSM4(&bh[0], bP + offB);
            LDSM4(&bh[4], bP + 4096 + offB);
#pragma unroll
            for (int mf = 0; mf < 2; mf++)
#pragma unroll
                for (int nf = 0; nf < 4; nf++)
                    MMA(acc[mf][nf], &ah[4 * mf], bh[2 * nf], bh[2 * nf + 1]);
        }

        bool diag = (rb == cb);

        // ---- row-side online epilogue ----
        int cbb[4];
#pragma unroll
        for (int nf = 0; nf < 4; nf++)
            cbb[nf] = (cb * 128 + nb + nf * 8) >> 4;
        int rbid0 = (rb * 128 + mb) >> 4;

#pragma unroll
        for (int mf = 0; mf < 2; mf++) {
            int rbid = rbid0 + mf;
#pragma unroll
            for (int h = 0; h < 2; h++) {
                int slot = mf * 2 + h;
                float v[8];
                float vmax = -3.0e38f;
                if (diag) {
#pragma unroll
                    for (int nf = 0; nf < 4; nf++) {
                        bool msk = (rbid == cbb[nf]);
                        float x0 = msk ? -3.0e38f : acc[mf][nf][2 * h];
                        float x1 = msk ? -3.0e38f : acc[mf][nf][2 * h + 1];
                        v[2 * nf] = x0; v[2 * nf + 1] = x1;
                        vmax = fmaxf(vmax, fmaxf(x0, x1));
                    }
                } else {
#pragma unroll
                    for (int nf = 0; nf < 4; nf++) {
                        float x0 = acc[mf][nf][2 * h];
                        float x1 = acc[mf][nf][2 * h + 1];
                        v[2 * nf] = x0; v[2 * nf + 1] = x1;
                        vmax = fmaxf(vmax, fmaxf(x0, x1));
                    }
                }
                vmax = fmaxf(vmax, __shfl_xor_sync(0xffffffffu, vmax, 1));
                vmax = fmaxf(vmax, __shfl_xor_sync(0xffffffffu, vmax, 2));
                float newM = fmaxf(m[slot], vmax);
                float s = 0.f;
                if (vmax > newM - 6.2f) {
#pragma unroll
                    for (int j = 0; j < 8; j++)
                        if (v[j] > newM - 6.2f)
                            s += __expf((v[j] - newM) * INV_T);
                }
                s += __shfl_xor_sync(0xffffffffu, s, 1);
                s += __shfl_xor_sync(0xffffffffu, s, 2);
                if (newM > m[slot]) {
                    lv[slot] = lv[slot] * __expf((m[slot] - newM) * INV_T) + s;
                    m[slot] = newM;
                } else {
                    lv[slot] += s;
                }
            }
        }

        // ---- col-side epilogue (off-diagonal only; smem merge) ----
        if (!diag) {
            float2* colred = (float2*)(smraw + (base - su) + SM_COLRED);
            float cm[8], cs[8];
#pragma unroll
            for (int nf = 0; nf < 4; nf++)
#pragma unroll
                for (int par = 0; par < 2; par++) {
                    int ix = nf * 2 + par;
                    float a0 = acc[0][nf][par],     a1 = acc[0][nf][2 + par];
                    float b0 = acc[1][nf][par],     b1 = acc[1][nf][2 + par];
                    float mx = fmaxf(fmaxf(a0, a1), fmaxf(b0, b1));
                    mx = fmaxf(mx, __shfl_xor_sync(0xffffffffu, mx, 4));
                    mx = fmaxf(mx, __shfl_xor_sync(0xffffffffu, mx, 8));
                    mx = fmaxf(mx, __shfl_xor_sync(0xffffffffu, mx, 16));
                    float s = 0.f;
                    if (a0 > mx - 6.2f) s += __expf((a0 - mx) * INV_T);
                    if (a1 > mx - 6.2f) s += __expf((a1 - mx) * INV_T);
                    if (b0 > mx - 6.2f) s += __expf((b0 - mx) * INV_T);
                    if (b1 > mx - 6.2f) s += __expf((b1 - mx) * INV_T);
                    s += __shfl_xor_sync(0xffffffffu, s, 4);
                    s += __shfl_xor_sync(0xffffffffu, s, 8);
                    s += __shfl_xor_sync(0xffffffffu, s, 16);
                    cm[ix] = mx; cs[ix] = s;
                }
            if (l < 4) {
#pragma unroll
                for (int nf = 0; nf < 4; nf++)
#pragma unroll
                    for (int par = 0; par < 2; par++)
                        colred[wy * 128 + nb + nf * 8 + 2 * l + par] =
                            make_float2(cm[nf * 2 + par], cs[nf * 2 + par]);
            }
            __syncthreads();
            if (tid < 128) {
                float2 p0 = colred[tid], p1 = colred[128 + tid];
                float2 p2 = colred[256 + tid], p3 = colred[384 + tid];
                float M = fmaxf(fmaxf(p0.x, p1.x), fmaxf(p2.x, p3.x));
                float L = p0.y * __expf((p0.x - M) * INV_T)
                        + p1.y * __expf((p1.x - M) * INV_T)
                        + p2.y * __expf((p2.x - M) * INV_T)
                        + p3.y * __expf((p3.x - M) * INV_T);
                g_slot[(size_t)(cb * 128 + tid) * 64 + rb] = make_float2(M, L);
            }
        }

        // ---- row-side flush at run end (rare) ----
        bool runend = !has_next || (rbn != rb);
        if (runend) {
            float2* rowred = (float2*)(smraw + (base - su) + SM_ROWRED);
            __syncthreads();
            if ((l & 3) == 0) {
                int g = l >> 2;
#pragma unroll
                for (int mf = 0; mf < 2; mf++)
#pragma unroll
                    for (int h = 0; h < 2; h++) {
                        int slot = mf * 2 + h;
                        rowred[(mb + mf * 16 + 8 * h + g) * 4 + wx] =
                            make_float2(m[slot], lv[slot]);
                    }
            }
            __syncthreads();
            if (tid < 128) {
                float2 p0 = rowred[tid * 4 + 0], p1 = rowred[tid * 4 + 1];
                float2 p2 = rowred[tid * 4 + 2], p3 = rowred[tid * 4 + 3];
                float M = fmaxf(fmaxf(p0.x, p1.x), fmaxf(p2.x, p3.x));
                float L = p0.y * __expf((p0.x - M) * INV_T)
                        + p1.y * __expf((p1.x - M) * INV_T)
                        + p2.y * __expf((p2.x - M) * INV_T)
                        + p3.y * __expf((p3.x - M) * INV_T);
                g_slot[(size_t)(rb * 128 + tid) * 64 + c0run] = make_float2(M, L);
            }
#pragma unroll
            for (int s = 0; s < 4; s++) { m[s] = -1.0e30f; lv[s] = 0.f; }
            c0run = cbn;
        }
        rb = rbn; cb = cbn;
    }
}

// ---------------- kernel 4: slot merge + per-row class-loss term (warp per row) ----------------
__global__ void finish_kernel(const float* __restrict__ f,
                              const int* __restrict__ labels) {
    int i = (blockIdx.x * blockDim.x + threadIdx.x) >> 5;
    int lane = threadIdx.x & 31;
    int b = i >> 4;
    int lab = labels[b];

    float4 q = ((const float4*)(g_slot + (size_t)i * 64))[lane];
    float2 s0 = make_float2(q.x, q.y), s1 = make_float2(q.z, q.w);
    float M = fmaxf(s0.x, s1.x);
    float L = s0.y * __expf((s0.x - M) * INV_T) + s1.y * __expf((s1.x - M) * INV_T);
#pragma unroll
    for (int sh = 16; sh > 0; sh >>= 1) {
        float Mo = __shfl_xor_sync(0xffffffffu, M, sh);
        float Lo = __shfl_xor_sync(0xffffffffu, L, sh);
        float Mn = fmaxf(M, Mo);
        L = L * __expf((M - Mn) * INV_T) + Lo * __expf((Mo - Mn) * INV_T);
        M = Mn;
    }

    float4 fv = ((const float4*)f)[i * 32 + lane];
    float4 Fv = ((const float4*)g_F)[lab * 32 + lane];
    float4 Bv = ((const float4*)g_Bb)[b * 32 + lane];
    float d = fv.x * (Fv.x - Bv.x) + fv.y * (Fv.y - Bv.y)
            + fv.z * (Fv.z - Bv.z) + fv.w * (Fv.w - Bv.w);
#pragma unroll
    for (int sh = 16; sh > 0; sh >>= 1)
        d += __shfl_xor_sync(0xffffffffu, d, sh);

    __shared__ float wterm[8];
    if (lane == 0) {
        float lse = M * INV_T + logf(L);
        float P = (float)(g_cnt[lab] * 16 - 16);
        float term = (P > 0.f) ? -(d * INV_T - P * lse) / (P + 1e-8f) : 0.f;
        wterm[threadIdx.x >> 5] = term;
    }
    __syncthreads();
    if (threadIdx.x == 0) {
        float ssum = 0.f;
#pragma unroll
        for (int w = 0; w < 8; w++) ssum += wterm[w];
        g_class_arr[blockIdx.x] = ssum;
    }
}

// ---------------- kernel 5: final scalar ----------------
__global__ void final_kernel(float* __restrict__ out) {
    __shared__ double shc[256], shn[256];
    int t = threadIdx.x;
    double c = 0.0, n = 0.0;
    for (int i = t; i < 1024; i += 256) c += (double)g_class_arr[i];
    for (int i = t; i < NBATCH; i += 256) n += (double)g_noise_arr[i];
    shc[t] = c; shn[t] = n;
    __syncthreads();
    for (int s = 128; s > 0; s >>= 1) {
        if (t < s) { shc[t] += shc[t + s]; shn[t] += shn[t + s]; }
        __syncthreads();
    }
    if (t == 0) {
        double loss_class = shc[0] / (double)N_ROWS;
        double s_noise_logits = shn[0] * (double)INV_T;
        double loss_noise = -(s_noise_logits / ((double)N_ROWS * 7.0)) / 0.07;
        double a = 1.0 / 3.0;
        out[0] = (float)(a * loss_class + a * loss_noise);
    }
}

// ---------------- launch ----------------
extern "C" void kernel_launch(void* const* d_in, const int* in_sizes, int n_in,
                              void* d_out, int out_size) {
    const float* f = (const float*)d_in[0];
    const int* labels = (const int*)d_in[1];
    float* out = (float*)d_out;

    cudaFuncSetAttribute(gram_kernel, cudaFuncAttributeMaxDynamicSharedMemorySize, SMEM_BYTES);

    setup_kernel<<<1024, 256>>>(f, labels);
    classsum_kernel<<<NBATCH, 128>>>(labels);
    gram_kernel<<<148, 512, SMEM_BYTES>>>();
    finish_kernel<<<1024, 256>>>(f, labels);
    final_kernel<<<1, 256>>>(out);
}

// round 8
// speedup vs baseline: 1.6865x; 1.0018x over previous
#include <cuda_runtime.h>
#include <cuda_fp16.h>
#include <math.h>
#include <stdint.h>

#define N_ROWS 8192
#define FD 128
#define INV_T 14.2857142857142857f   // 1/0.07
#define NBATCH 512
#define NCLASS 16

// ---------------- device-global scratch ----------------
__device__ uint4  g_f_sw[N_ROWS * 16];   // pre-swizzled fp16 features (tile-contiguous)
__device__ float  g_F[NCLASS * FD];
__device__ int    g_cnt[NCLASS];
__device__ float  g_Bb[NBATCH * FD];
__device__ __align__(16) float2 g_slot[N_ROWS * 64];  // per-(row, block) LSE partials
__device__ float  g_noise_arr[NBATCH];
__device__ float  g_class_arr[1024];

// ---------------- helpers ----------------
__device__ __forceinline__ uint32_t smem_u32(const void* p) {
    uint32_t a;
    asm("{ .reg .u64 t; cvta.to.shared.u64 t, %1; cvt.u32.u64 %0, t; }" : "=r"(a) : "l"(p));
    return a;
}
#define MBAR_INIT(bar, cnt) \
    asm volatile("mbarrier.init.shared.b64 [%0], %1;" :: "r"(bar), "r"(cnt) : "memory")
#define MBAR_EXPECT_TX(bar, bytes) \
    asm volatile("mbarrier.arrive.expect_tx.shared.b64 _, [%0], %1;" :: "r"(bar), "r"(bytes) : "memory")
#define BULK_G2S(dst, src, bytes, bar) \
    asm volatile("cp.async.bulk.shared::cluster.global.mbarrier::complete_tx::bytes [%0], [%1], %2, [%3];" \
                 :: "r"(dst), "l"(src), "r"(bytes), "r"(bar) : "memory")
#define FENCE_PROXY_ASYNC() asm volatile("fence.proxy.async.shared::cta;" ::: "memory")
#define MBAR_WAIT(bar, parity) do { \
    uint32_t _mm = (bar); uint32_t _pp = (parity); uint32_t _dd; \
    asm volatile("{ .reg .pred p; mbarrier.try_wait.parity.acquire.cta.shared::cta.b64 p, [%1], %2; selp.b32 %0, 1, 0, p; }" \
                 : "=r"(_dd) : "r"(_mm), "r"(_pp) : "memory"); \
    if (!_dd) { \
        asm volatile("{ .reg .pred P1; WL_%=: mbarrier.try_wait.parity.acquire.cta.shared::cta.b64 P1, [%0], %1, 0x989680; @P1 bra.uni WD_%=; bra.uni WL_%=; WD_%=: }" \
                     :: "r"(_mm), "r"(_pp) : "memory"); \
    } } while (0)

#define LDSM4(R, addr) \
    asm volatile("ldmatrix.sync.aligned.m8n8.x4.shared.b16 {%0,%1,%2,%3}, [%4];" \
        : "=r"((R)[0]), "=r"((R)[1]), "=r"((R)[2]), "=r"((R)[3]) : "r"(addr))

#define MMA(C, A, B0, B1) \
    asm volatile("mma.sync.aligned.m16n8k16.row.col.f32.f16.f16.f32 " \
        "{%0,%1,%2,%3}, {%4,%5,%6,%7}, {%8,%9}, {%0,%1,%2,%3};" \
        : "+f"((C)[0]), "+f"((C)[1]), "+f"((C)[2]), "+f"((C)[3]) \
        : "r"((A)[0]), "r"((A)[1]), "r"((A)[2]), "r"((A)[3]), "r"(B0), "r"(B1))

__device__ __forceinline__ uint32_t pack_h2(__half a, __half b) {
    __half2 t(a, b);
    return *reinterpret_cast<uint32_t*>(&t);
}

// ---------------- kernel 1: fused setup ----------------
__global__ void setup_kernel(const float* __restrict__ f, const int* __restrict__ labels) {
    __shared__ float red[8];
    int blk = blockIdx.x;
    int t = threadIdx.x;
    if (blk < 256) {
        float4* p = (float4*)g_slot;
        int base = (blk * 256 + t) * 4;
        float4 z = make_float4(-1.0e30f, 0.f, -1.0e30f, 0.f);
#pragma unroll
        for (int k = 0; k < 4; k++) p[base + k] = z;
        if (blk == 0) {
#pragma unroll
            for (int k = 0; k < 8; k++) g_F[t + 256 * k] = 0.f;
            if (t < NCLASS) g_cnt[t] = 0;
        }
    } else if (blk < 768) {
        int idx = (blk - 256) * 256 + t;
        int row = idx >> 4;
        int c = idx & 15;
        float4 v0 = ((const float4*)f)[row * 32 + c * 2];
        float4 v1 = ((const float4*)f)[row * 32 + c * 2 + 1];
        uint32_t h[4];
        h[0] = pack_h2(__float2half_rn(v0.x), __float2half_rn(v0.y));
        h[1] = pack_h2(__float2half_rn(v0.z), __float2half_rn(v0.w));
        h[2] = pack_h2(__float2half_rn(v1.x), __float2half_rn(v1.y));
        h[3] = pack_h2(__float2half_rn(v1.z), __float2half_rn(v1.w));
        int dst = ((row >> 7) << 11) + ((row & 127) << 4) + (c ^ (row & 7));
        g_f_sw[dst] = make_uint4(h[0], h[1], h[2], h[3]);
    } else {
        int b = (blk - 768) * 2 + (t >> 7);
        int tt = t & 127;
        float s16 = 0.f, s8a = 0.f, s8b = 0.f, ssq = 0.f;
#pragma unroll
        for (int r = 0; r < 16; r++) {
            float v = f[(b * 16 + r) * FD + tt];
            s16 += v;
            if (r < 8) s8a += v; else s8b += v;
            ssq += v * v;
        }
        g_Bb[b * FD + tt] = s16;
        float c = s8a * s8a + s8b * s8b - ssq;
#pragma unroll
        for (int sh = 16; sh > 0; sh >>= 1)
            c += __shfl_xor_sync(0xffffffffu, c, sh);
        if ((t & 31) == 0) red[t >> 5] = c;
        __syncthreads();
        if ((t & 127) == 0) {
            int w0 = t >> 5;
            g_noise_arr[b] = red[w0] + red[w0 + 1] + red[w0 + 2] + red[w0 + 3];
        }
    }
}

// ---------------- kernel 2: class sums ----------------
__global__ void classsum_kernel(const int* __restrict__ labels) {
    int b = blockIdx.x;
    int t = threadIdx.x;
    int lab = labels[b];
    atomicAdd(&g_F[lab * FD + t], g_Bb[b * FD + t]);
    if (t == 0) atomicAdd(&g_cnt[lab], 1);
}

// ---------------- kernel 3: pipelined symmetric fp16 HMMA gram ----------------
#define SM_A 0
#define SM_B(buf) (32768 + (buf) * 32768)
#define SM_COLRED 98304
#define SM_ROWRED 102400
#define SM_BARS 106496
#define SMEM_BYTES (106624 + 1024)
#define TILE_BYTES 32768u

// One pipelined iteration: issue MMA(i) into ACCC, then epilogue(i-1) on ACCP.
#define GRAM_ITER(I, ACCC, ACCP) do {                                          \
    int _i = (I);                                                               \
    bool do_mma = (_i < cnt);                                                   \
    int rbn = (cb == 63) ? rb + 1 : rb;                                         \
    int cbn = (cb == 63) ? rb + 1 : cb + 1;                                     \
    if (do_mma) {                                                               \
        if (_i == 0) { MBAR_WAIT(barA, 0); aPar = 1; }                          \
        else if (rb != a_cur) {                                                 \
            __syncthreads();                                                    \
            if (tid == 0) {                                                     \
                MBAR_EXPECT_TX(barA, TILE_BYTES);                               \
                BULK_G2S(base + SM_A, (const void*)(g_f_sw + rb * 2048), TILE_BYTES, barA); \
            }                                                                   \
            MBAR_WAIT(barA, aPar); aPar ^= 1; a_cur = rb;                       \
        }                                                                       \
        if (_i & 1) { MBAR_WAIT(barB1, bPar1); bPar1 ^= 1; }                    \
        else        { MBAR_WAIT(barB0, bPar0); bPar0 ^= 1; }                    \
        _Pragma("unroll")                                                       \
        for (int mf = 0; mf < 2; mf++)                                          \
            _Pragma("unroll")                                                   \
            for (int nf = 0; nf < 4; nf++)                                      \
                _Pragma("unroll")                                               \
                for (int r = 0; r < 4; r++) ACCC[mf][nf][r] = 0.f;              \
        uint32_t bP = base + SM_B(_i & 1) + (nb + rowB) * 256;                  \
        _Pragma("unroll")                                                       \
        for (int s = 0; s < 8; s++) {                                           \
            uint32_t offA = (uint32_t)(((2 * s + cA) ^ xA) << 4);               \
            uint32_t offB = (uint32_t)(((2 * s + cB) ^ xB) << 4);               \
            uint32_t ah[8], bh[8];                                              \
            LDSM4(&ah[0], aP + offA);                                           \
            LDSM4(&ah[4], aP + 4096 + offA);                                    \
            LDSM4(&bh[0], bP + offB);                                           \
            LDSM4(&bh[4], bP + 4096 + offB);                                    \
            _Pragma("unroll")                                                   \
            for (int mf = 0; mf < 2; mf++)                                      \
                _Pragma("unroll")                                               \
                for (int nf = 0; nf < 4; nf++)                                  \
                    MMA(ACCC[mf][nf], &ah[4 * mf], bh[2 * nf], bh[2 * nf + 1]); \
        }                                                                       \
        __syncthreads();                                                        \
        if (tid == 0 && _i + 2 < cnt) {                                         \
            int cb2 = (cbn == 63) ? rbn + 1 : cbn + 1;                          \
            uint32_t bN = (_i & 1) ? barB1 : barB0;                             \
            MBAR_EXPECT_TX(bN, TILE_BYTES);                                     \
            BULK_G2S(base + SM_B(_i & 1), (const void*)(g_f_sw + cb2 * 2048), TILE_BYTES, bN); \
        }                                                                       \
    }                                                                           \
    if (_i > 0) {                                                               \
        int cbb[4];                                                             \
        _Pragma("unroll")                                                       \
        for (int nf = 0; nf < 4; nf++)                                          \
            cbb[nf] = (pcb * 128 + nb + nf * 8) >> 4;                           \
        int rbid0 = (prb * 128 + mb) >> 4;                                      \
        _Pragma("unroll")                                                       \
        for (int mf = 0; mf < 2; mf++) {                                        \
            int rbid = rbid0 + mf;                                              \
            _Pragma("unroll")                                                   \
            for (int h = 0; h < 2; h++) {                                       \
                int slot = mf * 2 + h;                                          \
                float v[8];                                                     \
                float vmax = -3.0e38f;                                          \
                if (p_diag) {                                                   \
                    _Pragma("unroll")                                           \
                    for (int nf = 0; nf < 4; nf++) {                            \
                        bool msk = (rbid == cbb[nf]);                           \
                        float x0 = msk ? -3.0e38f : ACCP[mf][nf][2 * h];        \
                        float x1 = msk ? -3.0e38f : ACCP[mf][nf][2 * h + 1];    \
                        v[2 * nf] = x0; v[2 * nf + 1] = x1;                     \
                        vmax = fmaxf(vmax, fmaxf(x0, x1));                      \
                    }                                                           \
                } else {                                                        \
                    _Pragma("unroll")                                           \
                    for (int nf = 0; nf < 4; nf++) {                            \
                        float x0 = ACCP[mf][nf][2 * h];                         \
                        float x1 = ACCP[mf][nf][2 * h + 1];                     \
                        v[2 * nf] = x0; v[2 * nf + 1] = x1;                     \
                        vmax = fmaxf(vmax, fmaxf(x0, x1));                      \
                    }                                                           \
                }                                                               \
                vmax = fmaxf(vmax, __shfl_xor_sync(0xffffffffu, vmax, 1));      \
                vmax = fmaxf(vmax, __shfl_xor_sync(0xffffffffu, vmax, 2));      \
                float newM = fmaxf(m[slot], vmax);                              \
                float s = 0.f;                                                  \
                if (vmax > newM - 6.2f) {                                       \
                    _Pragma("unroll")                                           \
                    for (int j = 0; j < 8; j++)                                 \
                        if (v[j] > newM - 6.2f)                                 \
                            s += __expf((v[j] - newM) * INV_T);                 \
                }                                                               \
                s += __shfl_xor_sync(0xffffffffu, s, 1);                        \
                s += __shfl_xor_sync(0xffffffffu, s, 2);                        \
                if (newM > m[slot]) {                                           \
                    lv[slot] = lv[slot] * __expf((m[slot] - newM) * INV_T) + s; \
                    m[slot] = newM;                                             \
                } else {                                                        \
                    lv[slot] += s;                                              \
                }                                                               \
            }                                                                   \
        }                                                                       \
        if (!p_diag) {                                                          \
            float2* colred = (float2*)(cbptr + SM_COLRED);                      \
            float cm[8], cs[8];                                                 \
            _Pragma("unroll")                                                   \
            for (int nf = 0; nf < 4; nf++)                                      \
                _Pragma("unroll")                                               \
                for (int par = 0; par < 2; par++) {                             \
                    int ix = nf * 2 + par;                                      \
                    float a0 = ACCP[0][nf][par],   a1 = ACCP[0][nf][2 + par];   \
                    float b0 = ACCP[1][nf][par],   b1 = ACCP[1][nf][2 + par];   \
                    float mx = fmaxf(fmaxf(a0, a1), fmaxf(b0, b1));             \
                    mx = fmaxf(mx, __shfl_xor_sync(0xffffffffu, mx, 4));        \
                    mx = fmaxf(mx, __shfl_xor_sync(0xffffffffu, mx, 8));        \
                    mx = fmaxf(mx, __shfl_xor_sync(0xffffffffu, mx, 16));       \
                    float s = 0.f;                                              \
                    if (a0 > mx - 6.2f) s += __expf((a0 - mx) * INV_T);         \
                    if (a1 > mx - 6.2f) s += __expf((a1 - mx) * INV_T);         \
                    if (b0 > mx - 6.2f) s += __expf((b0 - mx) * INV_T);         \
                    if (b1 > mx - 6.2f) s += __expf((b1 - mx) * INV_T);         \
                    s += __shfl_xor_sync(0xffffffffu, s, 4);                    \
                    s += __shfl_xor_sync(0xffffffffu, s, 8);                    \
                    s += __shfl_xor_sync(0xffffffffu, s, 16);                   \
                    cm[ix] = mx; cs[ix] = s;                                    \
                }                                                               \
            if (l < 4) {                                                        \
                _Pragma("unroll")                                               \
                for (int nf = 0; nf < 4; nf++)                                  \
                    _Pragma("unroll")                                           \
                    for (int par = 0; par < 2; par++)                           \
                        colred[wy * 128 + nb + nf * 8 + 2 * l + par] =          \
                            make_float2(cm[nf * 2 + par], cs[nf * 2 + par]);    \
            }                                                                   \
            __syncthreads();                                                    \
            if (tid < 128) {                                                    \
                float2 p0 = colred[tid], p1 = colred[128 + tid];                \
                float2 p2 = colred[256 + tid], p3 = colred[384 + tid];          \
                float M = fmaxf(fmaxf(p0.x, p1.x), fmaxf(p2.x, p3.x));          \
                float L = p0.y * __expf((p0.x - M) * INV_T)                     \
                        + p1.y * __expf((p1.x - M) * INV_T)                     \
                        + p2.y * __expf((p2.x - M) * INV_T)                     \
                        + p3.y * __expf((p3.x - M) * INV_T);                    \
                g_slot[(size_t)(pcb * 128 + tid) * 64 + prb] = make_float2(M, L); \
            }                                                                   \
        }                                                                       \
        if (p_rend) {                                                           \
            float2* rowred = (float2*)(cbptr + SM_ROWRED);                      \
            __syncthreads();                                                    \
            if ((l & 3) == 0) {                                                 \
                int g = l >> 2;                                                 \
                _Pragma("unroll")                                               \
                for (int mf = 0; mf < 2; mf++)                                  \
                    _Pragma("unroll")                                           \
                    for (int h = 0; h < 2; h++) {                               \
                        int slot = mf * 2 + h;                                  \
                        rowred[(mb + mf * 16 + 8 * h + g) * 4 + wx] =           \
                            make_float2(m[slot], lv[slot]);                     \
                    }                                                           \
            }                                                                   \
            __syncthreads();                                                    \
            if (tid < 128) {                                                    \
                float2 p0 = rowred[tid * 4 + 0], p1 = rowred[tid * 4 + 1];      \
                float2 p2 = rowred[tid * 4 + 2], p3 = rowred[tid * 4 + 3];      \
                float M = fmaxf(fmaxf(p0.x, p1.x), fmaxf(p2.x, p3.x));          \
                float L = p0.y * __expf((p0.x - M) * INV_T)                     \
                        + p1.y * __expf((p1.x - M) * INV_T)                     \
                        + p2.y * __expf((p2.x - M) * INV_T)                     \
                        + p3.y * __expf((p3.x - M) * INV_T);                    \
                g_slot[(size_t)(prb * 128 + tid) * 64 + c0run] = make_float2(M, L); \
            }                                                                   \
            _Pragma("unroll")                                                   \
            for (int s = 0; s < 4; s++) { m[s] = -1.0e30f; lv[s] = 0.f; }       \
            if (do_mma) c0run = cb;                                             \
        }                                                                       \
    }                                                                           \
    prb = rb; pcb = cb; p_diag = (rb == cb);                                    \
    p_rend = (_i == cnt - 1) || (rbn != rb);                                    \
    rb = rbn; cb = cbn;                                                         \
} while (0)

__global__ void __launch_bounds__(512, 1) gram_kernel() {
    extern __shared__ char smraw[];
    uint32_t su = smem_u32(smraw);
    uint32_t base = (su + 1023u) & ~1023u;
    char* cbptr = smraw + (base - su);

    int tid = threadIdx.x;
    int l = tid & 31;
    int wid = tid >> 5;
    int wx = wid & 3, wy = wid >> 2;
    int mb = wy * 32, nb = wx * 32;

    uint32_t barA = base + SM_BARS;
    uint32_t barB0 = base + SM_BARS + 8;
    uint32_t barB1 = base + SM_BARS + 16;

    int cta = blockIdx.x;
    int t0 = cta * 14 + (cta < 8 ? cta : 8);
    int cnt = 14 + (cta < 8 ? 1 : 0);
    int rb = 0, off = 0;
    while (t0 >= off + (64 - rb)) { off += 64 - rb; rb++; }
    int cb = rb + (t0 - off);

    if (tid == 0) {
        MBAR_INIT(barA, 1);
        MBAR_INIT(barB0, 1);
        MBAR_INIT(barB1, 1);
        FENCE_PROXY_ASYNC();
    }
    __syncthreads();
    {
        int rb1 = (cb == 63) ? rb + 1 : rb;
        int cb1 = (cb == 63) ? rb + 1 : cb + 1;
        if (tid == 0) {
            MBAR_EXPECT_TX(barA, TILE_BYTES);
            BULK_G2S(base + SM_A, (const void*)(g_f_sw + rb * 2048), TILE_BYTES, barA);
            MBAR_EXPECT_TX(barB0, TILE_BYTES);
            BULK_G2S(base + SM_B(0), (const void*)(g_f_sw + cb * 2048), TILE_BYTES, barB0);
            if (cnt > 1) {
                MBAR_EXPECT_TX(barB1, TILE_BYTES);
                BULK_G2S(base + SM_B(1), (const void*)(g_f_sw + cb1 * 2048), TILE_BYTES, barB1);
            }
        }
        (void)rb1;
    }
    int aPar = 0, bPar0 = 0, bPar1 = 0;
    int a_cur = rb;

    int rowA = l & 15, cA = l >> 4, xA = rowA & 7;
    int rowB = (l & 7) + ((l >> 4) << 3), cB = (l >> 3) & 1, xB = rowB & 7;
    uint32_t aP = base + SM_A + (mb + rowA) * 256;

    float m[4], lv[4];
#pragma unroll
    for (int s = 0; s < 4; s++) { m[s] = -1.0e30f; lv[s] = 0.f; }
    float acc0[2][4][4], acc1[2][4][4];
    int c0run = cb;
    int prb = 0, pcb = 0;
    bool p_diag = false, p_rend = false;

    for (int ii = 0; ii <= cnt; ii += 2) {
        GRAM_ITER(ii, acc0, acc1);
        if (ii + 1 <= cnt) { GRAM_ITER(ii + 1, acc1, acc0); }
    }
}

// ---------------- kernel 4: slot merge + per-row class-loss term ----------------
__global__ void finish_kernel(const float* __restrict__ f,
                              const int* __restrict__ labels) {
    int i = (blockIdx.x * blockDim.x + threadIdx.x) >> 5;
    int lane = threadIdx.x & 31;
    int b = i >> 4;
    int lab = labels[b];

    float4 q = ((const float4*)(g_slot + (size_t)i * 64))[lane];
    float2 s0 = make_float2(q.x, q.y), s1 = make_float2(q.z, q.w);
    float M = fmaxf(s0.x, s1.x);
    float L = s0.y * __expf((s0.x - M) * INV_T) + s1.y * __expf((s1.x - M) * INV_T);
#pragma unroll
    for (int sh = 16; sh > 0; sh >>= 1) {
        float Mo = __shfl_xor_sync(0xffffffffu, M, sh);
        float Lo = __shfl_xor_sync(0xffffffffu, L, sh);
        float Mn = fmaxf(M, Mo);
        L = L * __expf((M - Mn) * INV_T) + Lo * __expf((Mo - Mn) * INV_T);
        M = Mn;
    }

    float4 fv = ((const float4*)f)[i * 32 + lane];
    float4 Fv = ((const float4*)g_F)[lab * 32 + lane];
    float4 Bv = ((const float4*)g_Bb)[b * 32 + lane];
    float d = fv.x * (Fv.x - Bv.x) + fv.y * (Fv.y - Bv.y)
            + fv.z * (Fv.z - Bv.z) + fv.w * (Fv.w - Bv.w);
#pragma unroll
    for (int sh = 16; sh > 0; sh >>= 1)
        d += __shfl_xor_sync(0xffffffffu, d, sh);

    __shared__ float wterm[8];
    if (lane == 0) {
        float lse = M * INV_T + logf(L);
        float P = (float)(g_cnt[lab] * 16 - 16);
        float term = (P > 0.f) ? -(d * INV_T - P * lse) / (P + 1e-8f) : 0.f;
        wterm[threadIdx.x >> 5] = term;
    }
    __syncthreads();
    if (threadIdx.x == 0) {
        float ssum = 0.f;
#pragma unroll
        for (int w = 0; w < 8; w++) ssum += wterm[w];
        g_class_arr[blockIdx.x] = ssum;
    }
}

// ---------------- kernel 5: final scalar ----------------
__global__ void final_kernel(float* __restrict__ out) {
    __shared__ double shc[256], shn[256];
    int t = threadIdx.x;
    double c = 0.0, n = 0.0;
    for (int i = t; i < 1024; i += 256) c += (double)g_class_arr[i];
    for (int i = t; i < NBATCH; i += 256) n += (double)g_noise_arr[i];
    shc[t] = c; shn[t] = n;
    __syncthreads();
    for (int s = 128; s > 0; s >>= 1) {
        if (t < s) { shc[t] += shc[t + s]; shn[t] += shn[t + s]; }
        __syncthreads();
    }
    if (t == 0) {
        double loss_class = shc[0] / (double)N_ROWS;
        double s_noise_logits = shn[0] * (double)INV_T;
        double loss_noise = -(s_noise_logits / ((double)N_ROWS * 7.0)) / 0.07;
        double a = 1.0 / 3.0;
        out[0] = (float)(a * loss_class + a * loss_noise);
    }
}

// ---------------- launch ----------------
extern "C" void kernel_launch(void* const* d_in, const int* in_sizes, int n_in,
                              void* d_out, int out_size) {
    const float* f = (const float*)d_in[0];
    const int* labels = (const int*)d_in[1];
    float* out = (float*)d_out;

    cudaFuncSetAttribute(gram_kernel, cudaFuncAttributeMaxDynamicSharedMemorySize, SMEM_BYTES);

    setup_kernel<<<1024, 256>>>(f, labels);
    classsum_kernel<<<NBATCH, 128>>>(labels);
    gram_kernel<<<148, 512, SMEM_BYTES>>>();
    finish_kernel<<<1024, 256>>>(f, labels);
    final_kernel<<<1, 256>>>(out);
}

// round 9
// speedup vs baseline: 1.7127x; 1.0155x over previous
#include <cuda_runtime.h>
#include <cuda_fp16.h>
#include <math.h>
#include <stdint.h>

#define N_ROWS 8192
#define FD 128
#define INV_T 14.2857142857142857f   // 1/0.07
#define NBATCH 512
#define NCLASS 16

// ---------------- device-global scratch ----------------
__device__ uint4  g_f_sw[N_ROWS * 16];   // pre-swizzled fp16 features (tile-contiguous)
__device__ float  g_F[NCLASS * FD];      // zeroed at module load + by last finish block
__device__ int    g_cnt[NCLASS];
__device__ float  g_Bb[NBATCH * FD];
__device__ __align__(16) float2 g_slot[N_ROWS * 64];  // (0,0) at load = identity partial
__device__ float  g_noise_arr[NBATCH];
__device__ float  g_class_arr[1024];
__device__ unsigned int g_ticket;        // self-resetting via atomicInc wrap

// ---------------- helpers ----------------
__device__ __forceinline__ uint32_t smem_u32(const void* p) {
    uint32_t a;
    asm("{ .reg .u64 t; cvta.to.shared.u64 t, %1; cvt.u32.u64 %0, t; }" : "=r"(a) : "l"(p));
    return a;
}
#define MBAR_INIT(bar, cnt) \
    asm volatile("mbarrier.init.shared.b64 [%0], %1;" :: "r"(bar), "r"(cnt) : "memory")
#define MBAR_EXPECT_TX(bar, bytes) \
    asm volatile("mbarrier.arrive.expect_tx.shared.b64 _, [%0], %1;" :: "r"(bar), "r"(bytes) : "memory")
#define BULK_G2S(dst, src, bytes, bar) \
    asm volatile("cp.async.bulk.shared::cluster.global.mbarrier::complete_tx::bytes [%0], [%1], %2, [%3];" \
                 :: "r"(dst), "l"(src), "r"(bytes), "r"(bar) : "memory")
#define FENCE_PROXY_ASYNC() asm volatile("fence.proxy.async.shared::cta;" ::: "memory")
#define MBAR_WAIT(bar, parity) do { \
    uint32_t _mm = (bar); uint32_t _pp = (parity); uint32_t _dd; \
    asm volatile("{ .reg .pred p; mbarrier.try_wait.parity.acquire.cta.shared::cta.b64 p, [%1], %2; selp.b32 %0, 1, 0, p; }" \
                 : "=r"(_dd) : "r"(_mm), "r"(_pp) : "memory"); \
    if (!_dd) { \
        asm volatile("{ .reg .pred P1; WL_%=: mbarrier.try_wait.parity.acquire.cta.shared::cta.b64 P1, [%0], %1, 0x989680; @P1 bra.uni WD_%=; bra.uni WL_%=; WD_%=: }" \
                     :: "r"(_mm), "r"(_pp) : "memory"); \
    } } while (0)

#define LDSM4(R, addr) \
    asm volatile("ldmatrix.sync.aligned.m8n8.x4.shared.b16 {%0,%1,%2,%3}, [%4];" \
        : "=r"((R)[0]), "=r"((R)[1]), "=r"((R)[2]), "=r"((R)[3]) : "r"(addr))

#define MMA(C, A, B0, B1) \
    asm volatile("mma.sync.aligned.m16n8k16.row.col.f32.f16.f16.f32 " \
        "{%0,%1,%2,%3}, {%4,%5,%6,%7}, {%8,%9}, {%0,%1,%2,%3};" \
        : "+f"((C)[0]), "+f"((C)[1]), "+f"((C)[2]), "+f"((C)[3]) \
        : "r"((A)[0]), "r"((A)[1]), "r"((A)[2]), "r"((A)[3]), "r"(B0), "r"(B1))

__device__ __forceinline__ uint32_t pack_h2(__half a, __half b) {
    __half2 t(a, b);
    return *reinterpret_cast<uint32_t*>(&t);
}

// ---------------- kernel 1: fused setup ----------------
// blocks [0,512): fp16 prep; [512,768): batch sums + noise + class-sum atomics
// (g_F/g_cnt are zero here: module load for run 1, last finish block thereafter)
__global__ void setup_kernel(const float* __restrict__ f, const int* __restrict__ labels) {
    __shared__ float red[8];
    int blk = blockIdx.x;
    int t = threadIdx.x;
    if (blk < 512) {
        int idx = blk * 256 + t;            // 0..131071, one 16B chunk
        int row = idx >> 4;
        int c = idx & 15;
        float4 v0 = ((const float4*)f)[row * 32 + c * 2];
        float4 v1 = ((const float4*)f)[row * 32 + c * 2 + 1];
        uint32_t h[4];
        h[0] = pack_h2(__float2half_rn(v0.x), __float2half_rn(v0.y));
        h[1] = pack_h2(__float2half_rn(v0.z), __float2half_rn(v0.w));
        h[2] = pack_h2(__float2half_rn(v1.x), __float2half_rn(v1.y));
        h[3] = pack_h2(__float2half_rn(v1.z), __float2half_rn(v1.w));
        int dst = ((row >> 7) << 11) + ((row & 127) << 4) + (c ^ (row & 7));
        g_f_sw[dst] = make_uint4(h[0], h[1], h[2], h[3]);
    } else {
        int b = (blk - 512) * 2 + (t >> 7);
        int tt = t & 127;
        float s16 = 0.f, s8a = 0.f, s8b = 0.f, ssq = 0.f;
#pragma unroll
        for (int r = 0; r < 16; r++) {
            float v = f[(b * 16 + r) * FD + tt];
            s16 += v;
            if (r < 8) s8a += v; else s8b += v;
            ssq += v * v;
        }
        g_Bb[b * FD + tt] = s16;
        int lab = labels[b];
        atomicAdd(&g_F[lab * FD + tt], s16);
        if (t == 0 || t == 128) atomicAdd(&g_cnt[lab], 1);
        float c = s8a * s8a + s8b * s8b - ssq;
#pragma unroll
        for (int sh = 16; sh > 0; sh >>= 1)
            c += __shfl_xor_sync(0xffffffffu, c, sh);
        if ((t & 31) == 0) red[t >> 5] = c;
        __syncthreads();
        if ((t & 127) == 0) {
            int w0 = t >> 5;
            g_noise_arr[b] = red[w0] + red[w0 + 1] + red[w0 + 2] + red[w0 + 3];
        }
    }
}

// ---------------- kernel 2: symmetric fp16 HMMA gram + two-sided LSE epilogue ----------------
#define SM_A 0
#define SM_B(buf) (32768 + (buf) * 32768)
#define SM_COLRED 98304
#define SM_ROWRED 102400
#define SM_BARS 106496
#define SMEM_BYTES (106624 + 1024)
#define TILE_BYTES 32768u

__global__ void __launch_bounds__(512, 1) gram_kernel() {
    extern __shared__ char smraw[];
    uint32_t su = smem_u32(smraw);
    uint32_t base = (su + 1023u) & ~1023u;

    int tid = threadIdx.x;
    int l = tid & 31;
    int wid = tid >> 5;
    int wx = wid & 3, wy = wid >> 2;
    int mb = wy * 32, nb = wx * 32;

    uint32_t barA = base + SM_BARS;
    uint32_t barB0 = base + SM_BARS + 8;
    uint32_t barB1 = base + SM_BARS + 16;

    // ---- tile range (triangular flat index over 2080 tiles, 148 CTAs) ----
    int cta = blockIdx.x;
    int t0 = cta * 14 + (cta < 8 ? cta : 8);
    int cnt = 14 + (cta < 8 ? 1 : 0);
    int rb = 0, off = 0;
    while (t0 >= off + (64 - rb)) { off += 64 - rb; rb++; }
    int cb = rb + (t0 - off);
    int c0run = cb;

    // ---- barriers + prologue bulk copies ----
    if (tid == 0) {
        MBAR_INIT(barA, 1);
        MBAR_INIT(barB0, 1);
        MBAR_INIT(barB1, 1);
        FENCE_PROXY_ASYNC();
    }
    __syncthreads();
    if (tid == 0) {
        MBAR_EXPECT_TX(barA, TILE_BYTES);
        BULK_G2S(base + SM_A, (const void*)(g_f_sw + rb * 2048), TILE_BYTES, barA);
        MBAR_EXPECT_TX(barB0, TILE_BYTES);
        BULK_G2S(base + SM_B(0), (const void*)(g_f_sw + cb * 2048), TILE_BYTES, barB0);
    }

    int a_cur = rb;
    int aPar = 0;
    bool a_ready = false;
    int bPar[2] = { 0, 0 };

    // ---- lane addressing ----
    int rowA = l & 15;
    int cA = l >> 4;
    int xA = rowA & 7;
    int rowB = (l & 7) + ((l >> 4) << 3);
    int cB = (l >> 3) & 1;
    int xB = rowB & 7;
    uint32_t aP = base + SM_A + (mb + rowA) * 256;

    float m[4], lv[4];
#pragma unroll
    for (int s = 0; s < 4; s++) { m[s] = -1.0e30f; lv[s] = 0.f; }

    for (int i = 0; i < cnt; i++) {
        int b = i & 1;
        bool has_next = (i + 1 < cnt);
        int rbn = rb, cbn = cb + 1;
        if (cb == 63) { rbn = rb + 1; cbn = rb + 1; }

        __syncthreads();   // prev tile fully consumed: buf b^1 / A / red areas free

        bool need_a = (rb != a_cur);
        if (tid == 0) {
            if (need_a) {
                MBAR_EXPECT_TX(barA, TILE_BYTES);
                BULK_G2S(base + SM_A, (const void*)(g_f_sw + rb * 2048), TILE_BYTES, barA);
            }
            if (has_next) {
                uint32_t barN = (b ^ 1) ? barB1 : barB0;
                MBAR_EXPECT_TX(barN, TILE_BYTES);
                BULK_G2S(base + SM_B(b ^ 1), (const void*)(g_f_sw + cbn * 2048), TILE_BYTES, barN);
            }
        }
        if (need_a) { a_cur = rb; a_ready = false; }
        if (!a_ready) { MBAR_WAIT(barA, aPar); aPar ^= 1; a_ready = true; }
        {
            uint32_t barC = b ? barB1 : barB0;
            MBAR_WAIT(barC, bPar[b]);
            bPar[b] ^= 1;
        }

        // ---- single-pass fp16 MMA ----
        float acc[2][4][4];
#pragma unroll
        for (int mf = 0; mf < 2; mf++)
#pragma unroll
            for (int nf = 0; nf < 4; nf++)
#pragma unroll
                for (int r = 0; r < 4; r++) acc[mf][nf][r] = 0.f;

        uint32_t bP = base + SM_B(b) + (nb + rowB) * 256;

#pragma unroll
        for (int s = 0; s < 8; s++) {
            uint32_t offA = (uint32_t)(((2 * s + cA) ^ xA) << 4);
            uint32_t offB = (uint32_t)(((2 * s + cB) ^ xB) << 4);
            uint32_t ah[8], bh[8];
            LDSM4(&ah[0], aP + offA);
            LDSM4(&ah[4], aP + 4096 + offA);
            LDSM4(&bh[0], bP + offB);
            LDSM4(&bh[4], bP + 4096 + offB);
#pragma unroll
            for (int mf = 0; mf < 2; mf++)
#pragma unroll
                for (int nf = 0; nf < 4; nf++)
                    MMA(acc[mf][nf], &ah[4 * mf], bh[2 * nf], bh[2 * nf + 1]);
        }

        bool diag = (rb == cb);

        // ---- row-side online epilogue ----
        int cbb[4];
#pragma unroll
        for (int nf = 0; nf < 4; nf++)
            cbb[nf] = (cb * 128 + nb + nf * 8) >> 4;
        int rbid0 = (rb * 128 + mb) >> 4;

#pragma unroll
        for (int mf = 0; mf < 2; mf++) {
            int rbid = rbid0 + mf;
#pragma unroll
            for (int h = 0; h < 2; h++) {
                int slot = mf * 2 + h;
                float v[8];
                float vmax = -3.0e38f;
                if (diag) {
#pragma unroll
                    for (int nf = 0; nf < 4; nf++) {
                        bool msk = (rbid == cbb[nf]);
                        float x0 = msk ? -3.0e38f : acc[mf][nf][2 * h];
                        float x1 = msk ? -3.0e38f : acc[mf][nf][2 * h + 1];
                        v[2 * nf] = x0; v[2 * nf + 1] = x1;
                        vmax = fmaxf(vmax, fmaxf(x0, x1));
                    }
                } else {
#pragma unroll
                    for (int nf = 0; nf < 4; nf++) {
                        float x0 = acc[mf][nf][2 * h];
                        float x1 = acc[mf][nf][2 * h + 1];
                        v[2 * nf] = x0; v[2 * nf + 1] = x1;
                        vmax = fmaxf(vmax, fmaxf(x0, x1));
                    }
                }
                vmax = fmaxf(vmax, __shfl_xor_sync(0xffffffffu, vmax, 1));
                vmax = fmaxf(vmax, __shfl_xor_sync(0xffffffffu, vmax, 2));
                float newM = fmaxf(m[slot], vmax);
                float s = 0.f;
                if (vmax > newM - 6.2f) {
#pragma unroll
                    for (int j = 0; j < 8; j++)
                        if (v[j] > newM - 6.2f)
                            s += __expf((v[j] - newM) * INV_T);
                }
                s += __shfl_xor_sync(0xffffffffu, s, 1);
                s += __shfl_xor_sync(0xffffffffu, s, 2);
                if (newM > m[slot]) {
                    lv[slot] = lv[slot] * __expf((m[slot] - newM) * INV_T) + s;
                    m[slot] = newM;
                } else {
                    lv[slot] += s;
                }
            }
        }

        // ---- col-side epilogue (off-diagonal only; smem merge) ----
        if (!diag) {
            float2* colred = (float2*)(smraw + (base - su) + SM_COLRED);
            float cm[8], cs[8];
#pragma unroll
            for (int nf = 0; nf < 4; nf++)
#pragma unroll
                for (int par = 0; par < 2; par++) {
                    int ix = nf * 2 + par;
                    float a0 = acc[0][nf][par],     a1 = acc[0][nf][2 + par];
                    float b0 = acc[1][nf][par],     b1 = acc[1][nf][2 + par];
                    float mx = fmaxf(fmaxf(a0, a1), fmaxf(b0, b1));
                    mx = fmaxf(mx, __shfl_xor_sync(0xffffffffu, mx, 4));
                    mx = fmaxf(mx, __shfl_xor_sync(0xffffffffu, mx, 8));
                    mx = fmaxf(mx, __shfl_xor_sync(0xffffffffu, mx, 16));
                    float s = 0.f;
                    if (a0 > mx - 6.2f) s += __expf((a0 - mx) * INV_T);
                    if (a1 > mx - 6.2f) s += __expf((a1 - mx) * INV_T);
                    if (b0 > mx - 6.2f) s += __expf((b0 - mx) * INV_T);
                    if (b1 > mx - 6.2f) s += __expf((b1 - mx) * INV_T);
                    s += __shfl_xor_sync(0xffffffffu, s, 4);
                    s += __shfl_xor_sync(0xffffffffu, s, 8);
                    s += __shfl_xor_sync(0xffffffffu, s, 16);
                    cm[ix] = mx; cs[ix] = s;
                }
            if (l < 4) {
#pragma unroll
                for (int nf = 0; nf < 4; nf++)
#pragma unroll
                    for (int par = 0; par < 2; par++)
                        colred[wy * 128 + nb + nf * 8 + 2 * l + par] =
                            make_float2(cm[nf * 2 + par], cs[nf * 2 + par]);
            }
            __syncthreads();
            if (tid < 128) {
                float2 p0 = colred[tid], p1 = colred[128 + tid];
                float2 p2 = colred[256 + tid], p3 = colred[384 + tid];
                float M = fmaxf(fmaxf(p0.x, p1.x), fmaxf(p2.x, p3.x));
                float L = p0.y * __expf((p0.x - M) * INV_T)
                        + p1.y * __expf((p1.x - M) * INV_T)
                        + p2.y * __expf((p2.x - M) * INV_T)
                        + p3.y * __expf((p3.x - M) * INV_T);
                g_slot[(size_t)(cb * 128 + tid) * 64 + rb] = make_float2(M, L);
            }
        }

        // ---- row-side flush at run end (rare) ----
        bool runend = !has_next || (rbn != rb);
        if (runend) {
            float2* rowred = (float2*)(smraw + (base - su) + SM_ROWRED);
            __syncthreads();
            if ((l & 3) == 0) {
                int g = l >> 2;
#pragma unroll
                for (int mf = 0; mf < 2; mf++)
#pragma unroll
                    for (int h = 0; h < 2; h++) {
                        int slot = mf * 2 + h;
                        rowred[(mb + mf * 16 + 8 * h + g) * 4 + wx] =
                            make_float2(m[slot], lv[slot]);
                    }
            }
            __syncthreads();
            if (tid < 128) {
                float2 p0 = rowred[tid * 4 + 0], p1 = rowred[tid * 4 + 1];
                float2 p2 = rowred[tid * 4 + 2], p3 = rowred[tid * 4 + 3];
                float M = fmaxf(fmaxf(p0.x, p1.x), fmaxf(p2.x, p3.x));
                float L = p0.y * __expf((p0.x - M) * INV_T)
                        + p1.y * __expf((p1.x - M) * INV_T)
                        + p2.y * __expf((p2.x - M) * INV_T)
                        + p3.y * __expf((p3.x - M) * INV_T);
                g_slot[(size_t)(rb * 128 + tid) * 64 + c0run] = make_float2(M, L);
            }
#pragma unroll
            for (int s = 0; s < 4; s++) { m[s] = -1.0e30f; lv[s] = 0.f; }
            c0run = cbn;
        }
        rb = rbn; cb = cbn;
    }
}

// ---------------- kernel 3: slot merge + class-loss + fused finale ----------------
__global__ void finish_kernel(const float* __restrict__ f,
                              const int* __restrict__ labels,
                              float* __restrict__ out) {
    int i = (blockIdx.x * blockDim.x + threadIdx.x) >> 5;
    int lane = threadIdx.x & 31;
    int b = i >> 4;
    int lab = labels[b];

    // merge 64 slots (2 per lane, then 5-level butterfly); (0,0) slots are identity
    float4 q = ((const float4*)(g_slot + (size_t)i * 64))[lane];
    float2 s0 = make_float2(q.x, q.y), s1 = make_float2(q.z, q.w);
    float M = fmaxf(s0.x, s1.x);
    float L = s0.y * __expf((s0.x - M) * INV_T) + s1.y * __expf((s1.x - M) * INV_T);
#pragma unroll
    for (int sh = 16; sh > 0; sh >>= 1) {
        float Mo = __shfl_xor_sync(0xffffffffu, M, sh);
        float Lo = __shfl_xor_sync(0xffffffffu, L, sh);
        float Mn = fmaxf(M, Mo);
        L = L * __expf((M - Mn) * INV_T) + Lo * __expf((Mo - Mn) * INV_T);
        M = Mn;
    }

    // closed-form positive sum (reads g_F before the ticket below)
    float4 fv = ((const float4*)f)[i * 32 + lane];
    float4 Fv = ((const float4*)g_F)[lab * 32 + lane];
    float4 Bv = ((const float4*)g_Bb)[b * 32 + lane];
    float d = fv.x * (Fv.x - Bv.x) + fv.y * (Fv.y - Bv.y)
            + fv.z * (Fv.z - Bv.z) + fv.w * (Fv.w - Bv.w);
#pragma unroll
    for (int sh = 16; sh > 0; sh >>= 1)
        d += __shfl_xor_sync(0xffffffffu, d, sh);

    __shared__ float wterm[8];
    __shared__ bool is_last;
    if (lane == 0) {
        float lse = M * INV_T + logf(L);
        float P = (float)(g_cnt[lab] * 16 - 16);
        float term = (P > 0.f) ? -(d * INV_T - P * lse) / (P + 1e-8f) : 0.f;
        wterm[threadIdx.x >> 5] = term;
    }
    __syncthreads();
    if (threadIdx.x == 0) {
        float ssum = 0.f;
#pragma unroll
        for (int w = 0; w < 8; w++) ssum += wterm[w];
        g_class_arr[blockIdx.x] = ssum;
        __threadfence();
        unsigned v = atomicInc(&g_ticket, 1023u);   // wraps to 0 at 1023 -> self-reset
        is_last = (v == 1023u);
    }
    __syncthreads();

    if (is_last) {
        __threadfence();
        __shared__ double shc[256], shn[256];
        int t = threadIdx.x;
        double c = 0.0, n = 0.0;
        for (int k = t; k < 1024; k += 256) c += (double)g_class_arr[k];
        for (int k = t; k < NBATCH; k += 256) n += (double)g_noise_arr[k];
        shc[t] = c; shn[t] = n;
        // zero g_F / g_cnt for the next graph replay
        for (int k = t; k < NCLASS * FD; k += 256) g_F[k] = 0.f;
        if (t < NCLASS) g_cnt[t] = 0;
        __syncthreads();
        for (int s = 128; s > 0; s >>= 1) {
            if (t < s) { shc[t] += shc[t + s]; shn[t] += shn[t + s]; }
            __syncthreads();
        }
        if (t == 0) {
            double loss_class = shc[0] / (double)N_ROWS;
            double s_noise_logits = shn[0] * (double)INV_T;
            double loss_noise = -(s_noise_logits / ((double)N_ROWS * 7.0)) / 0.07;
            double a = 1.0 / 3.0;
            out[0] = (float)(a * loss_class + a * loss_noise);
        }
    }
}

// ---------------- launch ----------------
extern "C" void kernel_launch(void* const* d_in, const int* in_sizes, int n_in,
                              void* d_out, int out_size) {
    const float* f = (const float*)d_in[0];
    const int* labels = (const int*)d_in[1];
    float* out = (float*)d_out;

    cudaFuncSetAttribute(gram_kernel, cudaFuncAttributeMaxDynamicSharedMemorySize, SMEM_BYTES);

    setup_kernel<<<768, 256>>>(f, labels);
    gram_kernel<<<148, 512, SMEM_BYTES>>>();
    finish_kernel<<<1024, 256>>>(f, labels, out);
}

// round 10
// speedup vs baseline: 1.9067x; 1.1133x over previous
#include <cuda_runtime.h>
#include <cuda_fp16.h>
#include <math.h>
#include <stdint.h>

#define N_ROWS 8192
#define FD 128
#define INV_T 14.2857142857142857f   // 1/0.07
#define NBATCH 512
#define NCLASS 16

// ---------------- device-global scratch ----------------
__device__ uint4  g_f_sw[N_ROWS * 16];   // pre-swizzled fp16 features (tile-contiguous)
__device__ float  g_F[NCLASS * FD];      // zeroed at module load + by last finish block
__device__ int    g_cnt[NCLASS];
__device__ float  g_Bb[NBATCH * FD];
__device__ __align__(16) float2 g_slot[N_ROWS * 64];  // (0,0) at load = identity partial
__device__ float  g_noise_arr[NBATCH];
__device__ float  g_class_arr[1024];
__device__ unsigned int g_ticket;

// ---------------- helpers ----------------
__device__ __forceinline__ uint32_t smem_u32(const void* p) {
    uint32_t a;
    asm("{ .reg .u64 t; cvta.to.shared.u64 t, %1; cvt.u32.u64 %0, t; }" : "=r"(a) : "l"(p));
    return a;
}
#define MBAR_INIT(bar, cnt) \
    asm volatile("mbarrier.init.shared.b64 [%0], %1;" :: "r"(bar), "r"(cnt) : "memory")
#define MBAR_EXPECT_TX(bar, bytes) \
    asm volatile("mbarrier.arrive.expect_tx.shared.b64 _, [%0], %1;" :: "r"(bar), "r"(bytes) : "memory")
#define BULK_G2S(dst, src, bytes, bar) \
    asm volatile("cp.async.bulk.shared::cluster.global.mbarrier::complete_tx::bytes [%0], [%1], %2, [%3];" \
                 :: "r"(dst), "l"(src), "r"(bytes), "r"(bar) : "memory")
#define FENCE_PROXY_ASYNC() asm volatile("fence.proxy.async.shared::cta;" ::: "memory")
#define MBAR_WAIT(bar, parity) do { \
    uint32_t _mm = (bar); uint32_t _pp = (parity); uint32_t _dd; \
    asm volatile("{ .reg .pred p; mbarrier.try_wait.parity.acquire.cta.shared::cta.b64 p, [%1], %2; selp.b32 %0, 1, 0, p; }" \
                 : "=r"(_dd) : "r"(_mm), "r"(_pp) : "memory"); \
    if (!_dd) { \
        asm volatile("{ .reg .pred P1; WL_%=: mbarrier.try_wait.parity.acquire.cta.shared::cta.b64 P1, [%0], %1, 0x989680; @P1 bra.uni WD_%=; bra.uni WL_%=; WD_%=: }" \
                     :: "r"(_mm), "r"(_pp) : "memory"); \
    } } while (0)

#define LDSM4(R, addr) \
    asm volatile("ldmatrix.sync.aligned.m8n8.x4.shared.b16 {%0,%1,%2,%3}, [%4];" \
        : "=r"((R)[0]), "=r"((R)[1]), "=r"((R)[2]), "=r"((R)[3]) : "r"(addr))

#define MMA(C, A, B0, B1) \
    asm volatile("mma.sync.aligned.m16n8k16.row.col.f32.f16.f16.f32 " \
        "{%0,%1,%2,%3}, {%4,%5,%6,%7}, {%8,%9}, {%0,%1,%2,%3};" \
        : "+f"((C)[0]), "+f"((C)[1]), "+f"((C)[2]), "+f"((C)[3]) \
        : "r"((A)[0]), "r"((A)[1]), "r"((A)[2]), "r"((A)[3]), "r"(B0), "r"(B1))

__device__ __forceinline__ uint32_t pack_h2(__half a, __half b) {
    __half2 t(a, b);
    return *reinterpret_cast<uint32_t*>(&t);
}

// ---------------- kernel 1: fused setup ----------------
__global__ void setup_kernel(const float* __restrict__ f, const int* __restrict__ labels) {
    __shared__ float red[8];
    int blk = blockIdx.x;
    int t = threadIdx.x;
    if (blk < 512) {
        int idx = blk * 256 + t;
        int row = idx >> 4;
        int c = idx & 15;
        float4 v0 = ((const float4*)f)[row * 32 + c * 2];
        float4 v1 = ((const float4*)f)[row * 32 + c * 2 + 1];
        uint32_t h[4];
        h[0] = pack_h2(__float2half_rn(v0.x), __float2half_rn(v0.y));
        h[1] = pack_h2(__float2half_rn(v0.z), __float2half_rn(v0.w));
        h[2] = pack_h2(__float2half_rn(v1.x), __float2half_rn(v1.y));
        h[3] = pack_h2(__float2half_rn(v1.z), __float2half_rn(v1.w));
        int dst = ((row >> 7) << 11) + ((row & 127) << 4) + (c ^ (row & 7));
        g_f_sw[dst] = make_uint4(h[0], h[1], h[2], h[3]);
    } else {
        int b = (blk - 512) * 2 + (t >> 7);
        int tt = t & 127;
        float s16 = 0.f, s8a = 0.f, s8b = 0.f, ssq = 0.f;
#pragma unroll
        for (int r = 0; r < 16; r++) {
            float v = f[(b * 16 + r) * FD + tt];
            s16 += v;
            if (r < 8) s8a += v; else s8b += v;
            ssq += v * v;
        }
        g_Bb[b * FD + tt] = s16;
        int lab = labels[b];
        atomicAdd(&g_F[lab * FD + tt], s16);
        if (t == 0 || t == 128) atomicAdd(&g_cnt[lab], 1);
        float c = s8a * s8a + s8b * s8b - ssq;
#pragma unroll
        for (int sh = 16; sh > 0; sh >>= 1)
            c += __shfl_xor_sync(0xffffffffu, c, sh);
        if ((t & 31) == 0) red[t >> 5] = c;
        __syncthreads();
        if ((t & 127) == 0) {
            int w0 = t >> 5;
            g_noise_arr[b] = red[w0] + red[w0 + 1] + red[w0 + 2] + red[w0 + 3];
        }
    }
}

// ---------------- kernel 2: 2-CTA/SM fp16 HMMA gram + two-sided LSE epilogue ----------------
// 296 CTAs x 256 threads (8 warps, warp tile 64x32), 128x128 CTA tiles.
#define SM_A 0
#define SM_B(buf) (32768 + (buf) * 32768)
#define SM_COLRED 98304
#define SM_ROWRED 100352
#define SM_BARS 104448
#define SMEM_BYTES (104576)
#define TILE_BYTES 32768u

__global__ void __launch_bounds__(256, 2) gram_kernel() {
    extern __shared__ char smraw[];
    uint32_t su = smem_u32(smraw);
    uint32_t base = (su + 1023u) & ~1023u;
    char* cbptr = smraw + (base - su);

    int tid = threadIdx.x;
    int l = tid & 31;
    int wid = tid >> 5;
    int wx = wid & 3, wy = wid >> 2;        // 4 x 2 warp grid
    int mb = wy * 64, nb = wx * 32;          // warp tile 64 rows x 32 cols

    uint32_t barA = base + SM_BARS;
    uint32_t barB0 = base + SM_BARS + 8;
    uint32_t barB1 = base + SM_BARS + 16;

    // ---- tile range: 2080 triangular tiles over 296 CTAs ----
    int cta = blockIdx.x;
    int t0 = cta * 7 + (cta < 8 ? cta : 8);
    int cnt = 7 + (cta < 8 ? 1 : 0);
    int rb = 0, off = 0;
    while (t0 >= off + (64 - rb)) { off += 64 - rb; rb++; }
    int cb = rb + (t0 - off);
    int c0run = cb;

    if (tid == 0) {
        MBAR_INIT(barA, 1);
        MBAR_INIT(barB0, 1);
        MBAR_INIT(barB1, 1);
        FENCE_PROXY_ASYNC();
    }
    __syncthreads();
    if (tid == 0) {
        MBAR_EXPECT_TX(barA, TILE_BYTES);
        BULK_G2S(base + SM_A, (const void*)(g_f_sw + rb * 2048), TILE_BYTES, barA);
        MBAR_EXPECT_TX(barB0, TILE_BYTES);
        BULK_G2S(base + SM_B(0), (const void*)(g_f_sw + cb * 2048), TILE_BYTES, barB0);
    }

    int a_cur = rb;
    int aPar = 0;
    bool a_ready = false;
    int bPar[2] = { 0, 0 };

    // ---- lane addressing ----
    int rowA = l & 15;
    int cA = l >> 4;
    int xA = rowA & 7;
    int rowB = (l & 7) + ((l >> 4) << 3);
    int cB = (l >> 3) & 1;
    int xB = rowB & 7;
    uint32_t aP = base + SM_A + (mb + rowA) * 256;

    float m[8], lv[8];
#pragma unroll
    for (int s = 0; s < 8; s++) { m[s] = -1.0e30f; lv[s] = 0.f; }

    for (int i = 0; i < cnt; i++) {
        int b = i & 1;
        bool has_next = (i + 1 < cnt);
        int rbn = rb, cbn = cb + 1;
        if (cb == 63) { rbn = rb + 1; cbn = rb + 1; }

        __syncthreads();   // prev tile fully consumed

        bool need_a = (rb != a_cur);
        if (tid == 0) {
            if (need_a) {
                MBAR_EXPECT_TX(barA, TILE_BYTES);
                BULK_G2S(base + SM_A, (const void*)(g_f_sw + rb * 2048), TILE_BYTES, barA);
            }
            if (has_next) {
                uint32_t barN = (b ^ 1) ? barB1 : barB0;
                MBAR_EXPECT_TX(barN, TILE_BYTES);
                BULK_G2S(base + SM_B(b ^ 1), (const void*)(g_f_sw + cbn * 2048), TILE_BYTES, barN);
            }
        }
        if (need_a) { a_cur = rb; a_ready = false; }
        if (!a_ready) { MBAR_WAIT(barA, aPar); aPar ^= 1; a_ready = true; }
        {
            uint32_t barC = b ? barB1 : barB0;
            MBAR_WAIT(barC, bPar[b]);
            bPar[b] ^= 1;
        }

        // ---- single-pass fp16 MMA: 4 mf x 4 nf ----
        float acc[4][4][4];
#pragma unroll
        for (int mf = 0; mf < 4; mf++)
#pragma unroll
            for (int nf = 0; nf < 4; nf++)
#pragma unroll
                for (int r = 0; r < 4; r++) acc[mf][nf][r] = 0.f;

        uint32_t bP = base + SM_B(b) + (nb + rowB) * 256;

#pragma unroll
        for (int s = 0; s < 8; s++) {
            uint32_t offA = (uint32_t)(((2 * s + cA) ^ xA) << 4);
            uint32_t offB = (uint32_t)(((2 * s + cB) ^ xB) << 4);
            uint32_t ah[16], bh[8];
            LDSM4(&ah[0],  aP + offA);
            LDSM4(&ah[4],  aP + 4096 + offA);
            LDSM4(&ah[8],  aP + 8192 + offA);
            LDSM4(&ah[12], aP + 12288 + offA);
            LDSM4(&bh[0],  bP + offB);
            LDSM4(&bh[4],  bP + 4096 + offB);
#pragma unroll
            for (int mf = 0; mf < 4; mf++)
#pragma unroll
                for (int nf = 0; nf < 4; nf++)
                    MMA(acc[mf][nf], &ah[4 * mf], bh[2 * nf], bh[2 * nf + 1]);
        }

        bool diag = (rb == cb);

        // ---- row-side online epilogue (8 slots: 4 mf x 2 h) ----
        int cbb[4];
#pragma unroll
        for (int nf = 0; nf < 4; nf++)
            cbb[nf] = (cb * 128 + nb + nf * 8) >> 4;
        int rbid0 = (rb * 128 + mb) >> 4;

#pragma unroll
        for (int mf = 0; mf < 4; mf++) {
            int rbid = rbid0 + mf;
#pragma unroll
            for (int h = 0; h < 2; h++) {
                int slot = mf * 2 + h;
                float v[8];
                float vmax = -3.0e38f;
                if (diag) {
#pragma unroll
                    for (int nf = 0; nf < 4; nf++) {
                        bool msk = (rbid == cbb[nf]);
                        float x0 = msk ? -3.0e38f : acc[mf][nf][2 * h];
                        float x1 = msk ? -3.0e38f : acc[mf][nf][2 * h + 1];
                        v[2 * nf] = x0; v[2 * nf + 1] = x1;
                        vmax = fmaxf(vmax, fmaxf(x0, x1));
                    }
                } else {
#pragma unroll
                    for (int nf = 0; nf < 4; nf++) {
                        float x0 = acc[mf][nf][2 * h];
                        float x1 = acc[mf][nf][2 * h + 1];
                        v[2 * nf] = x0; v[2 * nf + 1] = x1;
                        vmax = fmaxf(vmax, fmaxf(x0, x1));
                    }
                }
                vmax = fmaxf(vmax, __shfl_xor_sync(0xffffffffu, vmax, 1));
                vmax = fmaxf(vmax, __shfl_xor_sync(0xffffffffu, vmax, 2));
                float newM = fmaxf(m[slot], vmax);
                float s = 0.f;
                if (vmax > newM - 6.2f) {
#pragma unroll
                    for (int j = 0; j < 8; j++)
                        if (v[j] > newM - 6.2f)
                            s += __expf((v[j] - newM) * INV_T);
                }
                s += __shfl_xor_sync(0xffffffffu, s, 1);
                s += __shfl_xor_sync(0xffffffffu, s, 2);
                if (newM > m[slot]) {
                    lv[slot] = lv[slot] * __expf((m[slot] - newM) * INV_T) + s;
                    m[slot] = newM;
                } else {
                    lv[slot] += s;
                }
            }
        }

        // ---- col-side epilogue (off-diag only): reduce 64 rows per warp ----
        if (!diag) {
            float2* colred = (float2*)(cbptr + SM_COLRED);   // [2 wy][128 cols]
            float cm[8], cs[8];
#pragma unroll
            for (int nf = 0; nf < 4; nf++)
#pragma unroll
                for (int par = 0; par < 2; par++) {
                    int ix = nf * 2 + par;
                    float vv[8];
#pragma unroll
                    for (int mf = 0; mf < 4; mf++) {
                        vv[2 * mf] = acc[mf][nf][par];
                        vv[2 * mf + 1] = acc[mf][nf][2 + par];
                    }
                    float mx = vv[0];
#pragma unroll
                    for (int j = 1; j < 8; j++) mx = fmaxf(mx, vv[j]);
                    mx = fmaxf(mx, __shfl_xor_sync(0xffffffffu, mx, 4));
                    mx = fmaxf(mx, __shfl_xor_sync(0xffffffffu, mx, 8));
                    mx = fmaxf(mx, __shfl_xor_sync(0xffffffffu, mx, 16));
                    float s = 0.f;
#pragma unroll
                    for (int j = 0; j < 8; j++)
                        if (vv[j] > mx - 6.2f) s += __expf((vv[j] - mx) * INV_T);
                    s += __shfl_xor_sync(0xffffffffu, s, 4);
                    s += __shfl_xor_sync(0xffffffffu, s, 8);
                    s += __shfl_xor_sync(0xffffffffu, s, 16);
                    cm[ix] = mx; cs[ix] = s;
                }
            if (l < 4) {
#pragma unroll
                for (int nf = 0; nf < 4; nf++)
#pragma unroll
                    for (int par = 0; par < 2; par++)
                        colred[wy * 128 + nb + nf * 8 + 2 * l + par] =
                            make_float2(cm[nf * 2 + par], cs[nf * 2 + par]);
            }
            __syncthreads();
            if (tid < 128) {
                float2 p0 = colred[tid], p1 = colred[128 + tid];
                float M = fmaxf(p0.x, p1.x);
                float L = p0.y * __expf((p0.x - M) * INV_T)
                        + p1.y * __expf((p1.x - M) * INV_T);
                g_slot[(size_t)(cb * 128 + tid) * 64 + rb] = make_float2(M, L);
            }
        }

        // ---- row-side flush at run end ----
        bool runend = !has_next || (rbn != rb);
        if (runend) {
            float2* rowred = (float2*)(cbptr + SM_ROWRED);   // [128 rows][4 wx]
            __syncthreads();
            if ((l & 3) == 0) {
                int g = l >> 2;
#pragma unroll
                for (int mf = 0; mf < 4; mf++)
#pragma unroll
                    for (int h = 0; h < 2; h++) {
                        int slot = mf * 2 + h;
                        rowred[(mb + mf * 16 + 8 * h + g) * 4 + wx] =
                            make_float2(m[slot], lv[slot]);
                    }
            }
            __syncthreads();
            if (tid < 128) {
                float2 p0 = rowred[tid * 4 + 0], p1 = rowred[tid * 4 + 1];
                float2 p2 = rowred[tid * 4 + 2], p3 = rowred[tid * 4 + 3];
                float M = fmaxf(fmaxf(p0.x, p1.x), fmaxf(p2.x, p3.x));
                float L = p0.y * __expf((p0.x - M) * INV_T)
                        + p1.y * __expf((p1.x - M) * INV_T)
                        + p2.y * __expf((p2.x - M) * INV_T)
                        + p3.y * __expf((p3.x - M) * INV_T);
                g_slot[(size_t)(rb * 128 + tid) * 64 + c0run] = make_float2(M, L);
            }
#pragma unroll
            for (int s = 0; s < 8; s++) { m[s] = -1.0e30f; lv[s] = 0.f; }
            c0run = cbn;
        }
        rb = rbn; cb = cbn;
    }
}

// ---------------- kernel 3: slot merge + class-loss + fused finale ----------------
__global__ void finish_kernel(const float* __restrict__ f,
                              const int* __restrict__ labels,
                              float* __restrict__ out) {
    int i = (blockIdx.x * blockDim.x + threadIdx.x) >> 5;
    int lane = threadIdx.x & 31;
    int b = i >> 4;
    int lab = labels[b];

    float4 q = ((const float4*)(g_slot + (size_t)i * 64))[lane];
    float2 s0 = make_float2(q.x, q.y), s1 = make_float2(q.z, q.w);
    float M = fmaxf(s0.x, s1.x);
    float L = s0.y * __expf((s0.x - M) * INV_T) + s1.y * __expf((s1.x - M) * INV_T);
#pragma unroll
    for (int sh = 16; sh > 0; sh >>= 1) {
        float Mo = __shfl_xor_sync(0xffffffffu, M, sh);
        float Lo = __shfl_xor_sync(0xffffffffu, L, sh);
        float Mn = fmaxf(M, Mo);
        L = L * __expf((M - Mn) * INV_T) + Lo * __expf((Mo - Mn) * INV_T);
        M = Mn;
    }

    float4 fv = ((const float4*)f)[i * 32 + lane];
    float4 Fv = ((const float4*)g_F)[lab * 32 + lane];
    float4 Bv = ((const float4*)g_Bb)[b * 32 + lane];
    float d = fv.x * (Fv.x - Bv.x) + fv.y * (Fv.y - Bv.y)
            + fv.z * (Fv.z - Bv.z) + fv.w * (Fv.w - Bv.w);
#pragma unroll
    for (int sh = 16; sh > 0; sh >>= 1)
        d += __shfl_xor_sync(0xffffffffu, d, sh);

    __shared__ float wterm[8];
    __shared__ bool is_last;
    if (lane == 0) {
        float lse = M * INV_T + logf(L);
        float P = (float)(g_cnt[lab] * 16 - 16);
        float term = (P > 0.f) ? -(d * INV_T - P * lse) / (P + 1e-8f) : 0.f;
        wterm[threadIdx.x >> 5] = term;
    }
    __syncthreads();
    if (threadIdx.x == 0) {
        float ssum = 0.f;
#pragma unroll
        for (int w = 0; w < 8; w++) ssum += wterm[w];
        g_class_arr[blockIdx.x] = ssum;
        __threadfence();
        unsigned v = atomicInc(&g_ticket, 1023u);
        is_last = (v == 1023u);
    }
    __syncthreads();

    if (is_last) {
        __threadfence();
        __shared__ double shc[256], shn[256];
        int t = threadIdx.x;
        double c = 0.0, n = 0.0;
        for (int k = t; k < 1024; k += 256) c += (double)g_class_arr[k];
        for (int k = t; k < NBATCH; k += 256) n += (double)g_noise_arr[k];
        shc[t] = c; shn[t] = n;
        for (int k = t; k < NCLASS * FD; k += 256) g_F[k] = 0.f;
        if (t < NCLASS) g_cnt[t] = 0;
        __syncthreads();
        for (int s = 128; s > 0; s >>= 1) {
            if (t < s) { shc[t] += shc[t + s]; shn[t] += shn[t + s]; }
            __syncthreads();
        }
        if (t == 0) {
            double loss_class = shc[0] / (double)N_ROWS;
            double s_noise_logits = shn[0] * (double)INV_T;
            double loss_noise = -(s_noise_logits / ((double)N_ROWS * 7.0)) / 0.07;
            double a = 1.0 / 3.0;
            out[0] = (float)(a * loss_class + a * loss_noise);
        }
    }
}

// ---------------- launch ----------------
extern "C" void kernel_launch(void* const* d_in, const int* in_sizes, int n_in,
                              void* d_out, int out_size) {
    const float* f = (const float*)d_in[0];
    const int* labels = (const int*)d_in[1];
    float* out = (float*)d_out;

    cudaFuncSetAttribute(gram_kernel, cudaFuncAttributeMaxDynamicSharedMemorySize, SMEM_BYTES + 1024);

    setup_kernel<<<768, 256>>>(f, labels);
    gram_kernel<<<296, 256, SMEM_BYTES + 1024>>>();
    finish_kernel<<<1024, 256>>>(f, labels, out);
}